// round 9
// baseline (speedup 1.0000x reference)
#include <cuda_runtime.h>
#include <cuda_fp16.h>
#include <cstdint>

#define BB   4
#define LL   4096
#define DD   256
#define TILE 128
#define KT   16
#define SPAD 132
#define NJT  (LL / 128)

// ---------------------------------------------------------------------------
// Device scratch (allocation-free)
// ---------------------------------------------------------------------------
__device__ __align__(256) __half g_qhi[BB * LL * DD];
__device__ __align__(256) __half g_qlo[BB * LL * DD];
__device__ __align__(256) __half g_khi[BB * LL * DD];
__device__ __align__(256) __half g_klo[BB * LL * DD];
__device__ __align__(256) float  g_vp [BB * LL * DD];
__device__ __align__(256) float  g_S  [(size_t)BB * LL * LL];
__device__ __align__(256) float  g_c  [BB * LL];
__device__ __align__(256) float  g_pm [(size_t)BB * LL * NJT];
__device__ __align__(256) float  g_ps [(size_t)BB * LL * NJT];
__device__ __align__(256) __half g_vthi[BB * DD * LL];
__device__ __align__(256) __half g_vtlo[BB * DD * LL];

// ---------------------------------------------------------------------------
__device__ __forceinline__ void split_half(float x, __half& h, __half& l) {
    h = __float2half_rn(x);
    l = __float2half_rn(x - __half2float(h));
}

__device__ __forceinline__ unsigned long long ffma2(unsigned long long a,
                                                    unsigned long long b,
                                                    unsigned long long c) {
    unsigned long long d;
    asm("fma.rn.f32x2 %0, %1, %2, %3;" : "=l"(d) : "l"(a), "l"(b), "l"(c));
    return d;
}
__device__ __forceinline__ unsigned long long pack2(float x, float y) {
    unsigned long long r;
    asm("mov.b64 %0, {%1, %2};" : "=l"(r) : "f"(x), "f"(y));
    return r;
}
__device__ __forceinline__ float2 unpack2(unsigned long long p) {
    float2 r;
    asm("mov.b64 {%0, %1}, %2;" : "=f"(r.x), "=f"(r.y) : "l"(p));
    return r;
}

// ---------------------------------------------------------------------------
// Projection GEMM (FFMA2)
// ---------------------------------------------------------------------------
__global__ void __launch_bounds__(256, 2)
gemm_nt(const float* __restrict__ A, const float* __restrict__ Bm,
        const float* __restrict__ bias, float* __restrict__ C,
        __half* __restrict__ OHi, __half* __restrict__ OLo,
        int K, int N)
{
    __shared__ __align__(16) float As[KT][SPAD];
    __shared__ __align__(16) float Bs[KT][SPAD];

    const int t    = threadIdx.x;
    const int m0   = blockIdx.y * TILE;
    const int n0   = blockIdx.x * TILE;
    const int warp = t >> 5, lane = t & 31;
    const int tm = (warp & 1) * 64 + (lane & 7) * 8;
    const int tn = (warp >> 1) * 32 + (lane >> 3) * 8;

    unsigned long long acc[8][4];
#pragma unroll
    for (int i = 0; i < 8; i++)
#pragma unroll
        for (int j = 0; j < 4; j++) acc[i][j] = 0ull;

    for (int k0 = 0; k0 < K; k0 += KT) {
#pragma unroll
        for (int r = 0; r < 2; r++) {
            int idx = t + 256 * r;
            int row = idx >> 2;
            int c4  = (idx & 3) * 4;
            float4 av = *(const float4*)(A  + (size_t)(m0 + row) * K + k0 + c4);
            float4 bv = *(const float4*)(Bm + (size_t)(n0 + row) * K + k0 + c4);
            As[c4 + 0][row] = av.x; As[c4 + 1][row] = av.y;
            As[c4 + 2][row] = av.z; As[c4 + 3][row] = av.w;
            Bs[c4 + 0][row] = bv.x; Bs[c4 + 1][row] = bv.y;
            Bs[c4 + 2][row] = bv.z; Bs[c4 + 3][row] = bv.w;
        }
        __syncthreads();
#pragma unroll
        for (int k = 0; k < KT; k++) {
            float4 a0 = *(const float4*)&As[k][tm];
            float4 a1 = *(const float4*)&As[k][tm + 4];
            ulonglong2 b0 = *(const ulonglong2*)&Bs[k][tn];
            ulonglong2 b1 = *(const ulonglong2*)&Bs[k][tn + 4];
            float aa[8] = {a0.x, a0.y, a0.z, a0.w, a1.x, a1.y, a1.z, a1.w};
#pragma unroll
            for (int i = 0; i < 8; i++) {
                unsigned long long ad = pack2(aa[i], aa[i]);
                acc[i][0] = ffma2(ad, b0.x, acc[i][0]);
                acc[i][1] = ffma2(ad, b0.y, acc[i][1]);
                acc[i][2] = ffma2(ad, b1.x, acc[i][2]);
                acc[i][3] = ffma2(ad, b1.y, acc[i][3]);
            }
        }
        __syncthreads();
    }

#pragma unroll
    for (int i = 0; i < 8; i++) {
        size_t rowoff = (size_t)(m0 + tm + i) * N;
#pragma unroll
        for (int jp = 0; jp < 4; jp++) {
            int col = n0 + tn + jp * 2;
            float2 vv = unpack2(acc[i][jp]);
            vv.x += bias[col];
            vv.y += bias[col + 1];
            if (OHi) {
                __half h0, l0, h1, l1;
                split_half(vv.x, h0, l0);
                split_half(vv.y, h1, l1);
                __half2 hh; hh.x = h0; hh.y = h1;
                __half2 ll; ll.x = l0; ll.y = l1;
                *(__half2*)(OHi + rowoff + col) = hh;
                *(__half2*)(OLo + rowoff + col) = ll;
            } else {
                *(float2*)(C + rowoff + col) = vv;
            }
        }
    }
}

// ---------------------------------------------------------------------------
// mma.sync + ldmatrix + cp.async primitives
// ---------------------------------------------------------------------------
__device__ __forceinline__ void mma16816(float* d, const uint32_t* a, const uint32_t* b) {
    asm volatile(
        "mma.sync.aligned.m16n8k16.row.col.f32.f16.f16.f32 "
        "{%0,%1,%2,%3}, {%4,%5,%6,%7}, {%8,%9}, {%0,%1,%2,%3};"
        : "+f"(d[0]), "+f"(d[1]), "+f"(d[2]), "+f"(d[3])
        : "r"(a[0]), "r"(a[1]), "r"(a[2]), "r"(a[3]), "r"(b[0]), "r"(b[1]));
}
__device__ __forceinline__ void ldm_x4(uint32_t* r, uint32_t saddr) {
    asm volatile("ldmatrix.sync.aligned.m8n8.x4.shared.b16 {%0,%1,%2,%3}, [%4];"
                 : "=r"(r[0]), "=r"(r[1]), "=r"(r[2]), "=r"(r[3]) : "r"(saddr));
}
__device__ __forceinline__ uint32_t smem_u32p(const void* p) {
    uint32_t a;
    asm("{ .reg .u64 t; cvta.to.shared.u64 t, %1; cvt.u32.u64 %0, t; }"
        : "=r"(a) : "l"(p));
    return a;
}
__device__ __forceinline__ void cp_async16(uint32_t saddr, const void* g) {
    asm volatile("cp.async.cg.shared.global [%0], [%1], 16;"
                 :: "r"(saddr), "l"(g) : "memory");
}
#define CP_COMMIT()  asm volatile("cp.async.commit_group;" ::: "memory")
#define CP_WAIT1()   asm volatile("cp.async.wait_group 1;" ::: "memory")

#define SROW   40
#define PITCH  (SROW * 2)           // 80 B
#define OPSZ   (128 * PITCH)        // 10240 B
#define BUFSZ  (4 * OPSZ)
#define MMA_DYN (2 * BUFSZ)

// ---------------------------------------------------------------------------
// Score GEMM + per-tile softmax partials (unchanged from R8)
// ---------------------------------------------------------------------------
#define K16_STEP(ks, aoffh, aoffl, boffh, boffl)                               \
    do {                                                                       \
        uint32_t ah[4][4], al[4][4], bh[4][2], bl[4][2];                       \
        _Pragma("unroll")                                                      \
        for (int mt = 0; mt < 4; mt++) {                                       \
            uint32_t ra = (uint32_t)(wm * 64 + mt * 16 + lar) * PITCH          \
                        + ((ks) + lac) * 2;                                    \
            ldm_x4(ah[mt], (aoffh) + ra);                                      \
            ldm_x4(al[mt], (aoffl) + ra);                                      \
        }                                                                      \
        _Pragma("unroll")                                                      \
        for (int pp = 0; pp < 2; pp++) {                                       \
            uint32_t rb = (uint32_t)(wn * 32 + pp * 16 + lbr) * PITCH          \
                        + ((ks) + lbc) * 2;                                    \
            uint32_t tb[4];                                                    \
            ldm_x4(tb, (boffh) + rb);                                          \
            bh[2 * pp][0] = tb[0]; bh[2 * pp][1] = tb[1];                      \
            bh[2 * pp + 1][0] = tb[2]; bh[2 * pp + 1][1] = tb[3];              \
            ldm_x4(tb, (boffl) + rb);                                          \
            bl[2 * pp][0] = tb[0]; bl[2 * pp][1] = tb[1];                      \
            bl[2 * pp + 1][0] = tb[2]; bl[2 * pp + 1][1] = tb[3];              \
        }                                                                      \
        _Pragma("unroll")                                                      \
        for (int mt = 0; mt < 4; mt++)                                         \
            _Pragma("unroll")                                                  \
            for (int nt = 0; nt < 4; nt++) {                                   \
                mma16816(acc[mt][nt], ah[mt], bh[nt]);                         \
                mma16816(acc[mt][nt], ah[mt], bl[nt]);                         \
                mma16816(acc[mt][nt], al[mt], bh[nt]);                         \
            }                                                                  \
    } while (0)

__global__ void __launch_bounds__(256)
score_mma(const __half* __restrict__ Ahg, const __half* __restrict__ Alg,
          const __half* __restrict__ Bhg, const __half* __restrict__ Blg,
          float* __restrict__ C, float* __restrict__ pm, float* __restrict__ ps,
          float scale)
{
    extern __shared__ __align__(16) char dyn[];
    const uint32_t su = smem_u32p(dyn);
    __shared__ float redm[128][4];
    __shared__ float redl[128][4];
    __shared__ float redmax[128];

    const int t = threadIdx.x;
    const int wid = t >> 5, lane = t & 31;
    const int wm = wid >> 2;
    const int wn = wid & 3;
    const int fr = lane >> 2;
    const int fc = (lane & 3) * 2;
    const int lar = (lane & 7) + ((lane >> 3) & 1) * 8;
    const int lac = (lane >> 4) * 8;
    const int lbr = (lane & 7) + (lane >> 4) * 8;
    const int lbc = ((lane >> 3) & 1) * 8;

    const size_t zqk = (size_t)LL * DD;
    Ahg += (size_t)blockIdx.z * zqk;  Alg += (size_t)blockIdx.z * zqk;
    Bhg += (size_t)blockIdx.z * zqk;  Blg += (size_t)blockIdx.z * zqk;
    C   += (size_t)blockIdx.z * LL * LL;
    const int m0 = blockIdx.y * 128;
    const int n0 = blockIdx.x * 128;

    float acc[4][4][4];
#pragma unroll
    for (int i = 0; i < 4; i++)
#pragma unroll
        for (int j = 0; j < 4; j++)
#pragma unroll
            for (int e = 0; e < 4; e++) acc[i][j][e] = 0.0f;

    const int srow = t >> 2;
    const int sq   = (t & 3) * 8;

    auto stage = [&](int b, int k0) {
        const uint32_t base = su + b * BUFSZ;
#pragma unroll
        for (int it = 0; it < 2; it++) {
            int row = srow + 64 * it;
            uint32_t so = base + row * PITCH + sq * 2;
            size_t ea = (size_t)(m0 + row) * DD + k0 + sq;
            size_t eb = (size_t)(n0 + row) * DD + k0 + sq;
            cp_async16(so + 0 * OPSZ, Ahg + ea);
            cp_async16(so + 1 * OPSZ, Alg + ea);
            cp_async16(so + 2 * OPSZ, Bhg + eb);
            cp_async16(so + 3 * OPSZ, Blg + eb);
        }
    };

    const int nchunks = DD >> 5;
    stage(0, 0);
    CP_COMMIT();

    for (int kc = 0; kc < nchunks; kc++) {
        if (kc + 1 < nchunks) stage((kc + 1) & 1, (kc + 1) << 5);
        CP_COMMIT();
        CP_WAIT1();
        __syncthreads();

        const uint32_t bb = su + (kc & 1) * BUFSZ;
        K16_STEP(0,  bb, bb + OPSZ, bb + 2 * OPSZ, bb + 3 * OPSZ);
        K16_STEP(16, bb, bb + OPSZ, bb + 2 * OPSZ, bb + 3 * OPSZ);
        __syncthreads();
    }

#pragma unroll
    for (int mt = 0; mt < 4; mt++) {
        int row = m0 + wm * 64 + mt * 16 + fr;
#pragma unroll
        for (int nt = 0; nt < 4; nt++) {
            int col = n0 + wn * 32 + nt * 8 + fc;
            float2 v0, v1;
            v0.x = acc[mt][nt][0] * scale;
            v0.y = acc[mt][nt][1] * scale;
            v1.x = acc[mt][nt][2] * scale;
            v1.y = acc[mt][nt][3] * scale;
            *(float2*)(C + (size_t)row * LL + col)       = v0;
            *(float2*)(C + (size_t)(row + 8) * LL + col) = v1;
        }
    }

    float rm[4][2];
#pragma unroll
    for (int mt = 0; mt < 4; mt++)
#pragma unroll
        for (int h = 0; h < 2; h++) {
            float m = -3.0e38f;
#pragma unroll
            for (int nt = 0; nt < 4; nt++) {
                m = fmaxf(m, acc[mt][nt][2 * h]     * scale);
                m = fmaxf(m, acc[mt][nt][2 * h + 1] * scale);
            }
#pragma unroll
            for (int o = 1; o <= 2; o <<= 1)
                m = fmaxf(m, __shfl_xor_sync(0xffffffffu, m, o));
            rm[mt][h] = m;
        }
    if ((lane & 3) == 0) {
#pragma unroll
        for (int mt = 0; mt < 4; mt++)
#pragma unroll
            for (int h = 0; h < 2; h++)
                redm[wm * 64 + mt * 16 + fr + 8 * h][wn] = rm[mt][h];
    }
    __syncthreads();
    if (t < 128)
        redmax[t] = fmaxf(fmaxf(redm[t][0], redm[t][1]),
                          fmaxf(redm[t][2], redm[t][3]));
    __syncthreads();
#pragma unroll
    for (int mt = 0; mt < 4; mt++)
#pragma unroll
        for (int h = 0; h < 2; h++) {
            int r = wm * 64 + mt * 16 + fr + 8 * h;
            float rmx = redmax[r];
            float s = 0.0f;
#pragma unroll
            for (int nt = 0; nt < 4; nt++) {
                s += __expf(acc[mt][nt][2 * h]     * scale - rmx);
                s += __expf(acc[mt][nt][2 * h + 1] * scale - rmx);
            }
#pragma unroll
            for (int o = 1; o <= 2; o <<= 1)
                s += __shfl_xor_sync(0xffffffffu, s, o);
            if ((lane & 3) == 0) redl[r][wn] = s;
        }
    __syncthreads();
    if (t < 128) {
        float sum = redl[t][0] + redl[t][1] + redl[t][2] + redl[t][3];
        size_t o = ((size_t)blockIdx.z * LL + m0 + t) * NJT + blockIdx.x;
        pm[o] = redmax[t];
        ps[o] = sum;
    }
}

// ---------------------------------------------------------------------------
// Combine partials
// ---------------------------------------------------------------------------
__global__ void __launch_bounds__(256)
combine(const float* __restrict__ pm, const float* __restrict__ ps,
        float* __restrict__ c)
{
    const int row = blockIdx.x * 8 + threadIdx.y;
    const int tx  = threadIdx.x;
    size_t base = (size_t)row * NJT + tx;
    float m = pm[base];
    float l = ps[base];
    float M = m;
#pragma unroll
    for (int o = 16; o > 0; o >>= 1)
        M = fmaxf(M, __shfl_xor_sync(0xffffffffu, M, o));
    float s = l * __expf(m - M);
#pragma unroll
    for (int o = 16; o > 0; o >>= 1)
        s += __shfl_xor_sync(0xffffffffu, s, o);
    if (tx == 0) c[row] = M + __logf(s);
}

// ---------------------------------------------------------------------------
// Fused output GEMM, full-D tile (128j x 256d), 512 threads, one wave.
// out[b,j,d] = sum_i exp(S[b,i,j]-c[b,i]) * V'[b,i,d]
// S read ONCE; A operand built on the fly (exp + split + transpose).
// ---------------------------------------------------------------------------
#define AO2_SSZ   (32 * 132 * 4)          // 16896 per S buffer
#define AO2_AH    (2 * AO2_SSZ)           // 33792
#define AO2_AL    (AO2_AH + OPSZ)         // 44032
#define AO2_B0    (AO2_AL + OPSZ)         // 54272
#define AO2_BOP   (256 * PITCH)           // 20480 per operand
#define AO2_BBUF  (2 * AO2_BOP)           // 40960 per buffer
#define AO2_DYN   (AO2_B0 + 2 * AO2_BBUF) // 136192 B

__global__ void __launch_bounds__(512)
attn_out_fused(const float* __restrict__ S, const float* __restrict__ cst,
               const __half* __restrict__ Vth, const __half* __restrict__ Vtl,
               float* __restrict__ out)
{
    extern __shared__ __align__(16) char dyn[];
    __shared__ float sc[32];
    const uint32_t su = smem_u32p(dyn);

    const int t = threadIdx.x;
    const int wid = t >> 5, lane = t & 31;
    const int wm = wid >> 2;          // j-axis warp (0..3), 32 rows each
    const int wn = wid & 3;           // d-axis warp (0..3), 64 cols each
    const int fr = lane >> 2;
    const int fc = (lane & 3) * 2;
    const int lar = (lane & 7) + ((lane >> 3) & 1) * 8;
    const int lac = (lane >> 4) * 8;
    const int lbr = (lane & 7) + (lane >> 4) * 8;
    const int lbc = ((lane >> 3) & 1) * 8;

    const int b = blockIdx.z;
    const float* Sb  = S   + (size_t)b * LL * LL;
    const float* cb  = cst + (size_t)b * LL;
    const __half* Vh = Vth + (size_t)b * DD * LL;
    const __half* Vl = Vtl + (size_t)b * DD * LL;
    float* Ob = out + (size_t)b * LL * DD;

    const int j0 = blockIdx.y * 128;

    float acc[2][8][4];
#pragma unroll
    for (int i = 0; i < 2; i++)
#pragma unroll
        for (int j = 0; j < 8; j++)
#pragma unroll
            for (int e = 0; e < 4; e++) acc[i][j][e] = 0.0f;

    const int srow = t >> 2;          // 0..127
    const int sq   = (t & 3) * 8;

    auto stageB = [&](int buf, int i0) {
        const uint32_t base = su + AO2_B0 + buf * AO2_BBUF;
#pragma unroll
        for (int it = 0; it < 2; it++) {
            int row = srow + 128 * it;        // 0..255 (d rows)
            uint32_t so = base + row * PITCH + sq * 2;
            size_t e = (size_t)row * LL + i0 + sq;
            cp_async16(so,           Vh + e);
            cp_async16(so + AO2_BOP, Vl + e);
        }
    };
    auto stageS = [&](int buf, int i0) {
        const uint32_t base = su + buf * AO2_SSZ;
#pragma unroll
        for (int u = 0; u < 2; u++) {
            int idx = t + 512 * u;            // 1024 16B slots
            int row = idx >> 5;               // 0..31
            int c4  = (idx & 31) * 4;
            cp_async16(base + row * 528 + c4 * 4,
                       Sb + (size_t)(i0 + row) * LL + j0 + c4);
        }
    };

    const int nchunks = LL >> 5;       // 128
    stageB(0, 0);
    stageS(0, 0);
    CP_COMMIT();

    const int jl  = t & 127;           // transform j column
    const int ih8 = (t >> 7) * 8;      // i sub-block (0,8,16,24)

    for (int kc = 0; kc < nchunks; kc++) {
        const int i0 = kc << 5;
        if (kc + 1 < nchunks) {
            stageB((kc + 1) & 1, i0 + 32);
            stageS((kc + 1) & 1, i0 + 32);
        }
        CP_COMMIT();
        CP_WAIT1();
        if (t < 32) sc[t] = cb[i0 + t];
        __syncthreads();

        // ---- transform: exp + split + transpose into A tiles [j][i] ----
        {
            const float* sSp = (const float*)(dyn + (kc & 1) * AO2_SSZ);
            __half2 hb[4], lb[4];
#pragma unroll
            for (int ii = 0; ii < 8; ii += 2) {
                float s0 = sSp[(ih8 + ii)     * 132 + jl];
                float s1 = sSp[(ih8 + ii + 1) * 132 + jl];
                float p0 = __expf(s0 - sc[ih8 + ii]);
                float p1 = __expf(s1 - sc[ih8 + ii + 1]);
                __half h0 = __float2half_rn(p0);
                __half h1 = __float2half_rn(p1);
                __half l0 = __float2half_rn(p0 - __half2float(h0));
                __half l1 = __float2half_rn(p1 - __half2float(h1));
                hb[ii >> 1] = __halves2half2(h0, h1);
                lb[ii >> 1] = __halves2half2(l0, l1);
            }
            *(uint4*)(dyn + AO2_AH + jl * PITCH + ih8 * 2) = *(uint4*)hb;
            *(uint4*)(dyn + AO2_AL + jl * PITCH + ih8 * 2) = *(uint4*)lb;
        }
        __syncthreads();

        // ---- MMA over the 32-i chunk ----
        const uint32_t aoh = su + AO2_AH;
        const uint32_t aol = su + AO2_AL;
        const uint32_t bbh = su + AO2_B0 + (kc & 1) * AO2_BBUF;
        const uint32_t bbl = bbh + AO2_BOP;

#pragma unroll
        for (int ks = 0; ks < 32; ks += 16) {
            uint32_t ah[2][4], al[2][4];
#pragma unroll
            for (int mt = 0; mt < 2; mt++) {
                uint32_t ra = (uint32_t)(wm * 32 + mt * 16 + lar) * PITCH
                            + (ks + lac) * 2;
                ldm_x4(ah[mt], aoh + ra);
                ldm_x4(al[mt], aol + ra);
            }
#pragma unroll
            for (int pp = 0; pp < 4; pp++) {
                uint32_t rb = (uint32_t)(wn * 64 + pp * 16 + lbr) * PITCH
                            + (ks + lbc) * 2;
                uint32_t tbh[4], tbl[4];
                ldm_x4(tbh, bbh + rb);
                ldm_x4(tbl, bbl + rb);
#pragma unroll
                for (int mt = 0; mt < 2; mt++) {
                    mma16816(acc[mt][2 * pp],     ah[mt], tbh);
                    mma16816(acc[mt][2 * pp],     ah[mt], tbl);
                    mma16816(acc[mt][2 * pp],     al[mt], tbh);
                    mma16816(acc[mt][2 * pp + 1], ah[mt], tbh + 2);
                    mma16816(acc[mt][2 * pp + 1], ah[mt], tbl + 2);
                    mma16816(acc[mt][2 * pp + 1], al[mt], tbh + 2);
                }
            }
        }
        __syncthreads();
    }

    // ---- epilogue: out[j][d], d0 = 0 (full D tile) ----
#pragma unroll
    for (int mt = 0; mt < 2; mt++) {
        int row = j0 + wm * 32 + mt * 16 + fr;
#pragma unroll
        for (int nt = 0; nt < 8; nt++) {
            int col = wn * 64 + nt * 8 + fc;
            float2 v0, v1;
            v0.x = acc[mt][nt][0];
            v0.y = acc[mt][nt][1];
            v1.x = acc[mt][nt][2];
            v1.y = acc[mt][nt][3];
            *(float2*)(Ob + (size_t)row * DD + col)       = v0;
            *(float2*)(Ob + (size_t)(row + 8) * DD + col) = v1;
        }
    }
}

// ---------------------------------------------------------------------------
// V^T build
// ---------------------------------------------------------------------------
__global__ void __launch_bounds__(256)
v_split_t(const float* __restrict__ V,
          __half* __restrict__ Vhi, __half* __restrict__ Vlo)
{
    const int b = blockIdx.z;
    const float* Vb = V + (size_t)b * LL * DD;
    __shared__ float tile[32][33];
    const int tx = threadIdx.x, ty = threadIdx.y;
    const int d0 = blockIdx.x * 32, i0 = blockIdx.y * 32;

#pragma unroll
    for (int r = 0; r < 4; r++) {
        int i = i0 + ty + r * 8;
        tile[ty + r * 8][tx] = Vb[(size_t)i * DD + d0 + tx];
    }
    __syncthreads();
    const size_t ob = (size_t)b * DD * LL;
#pragma unroll
    for (int r = 0; r < 4; r++) {
        int d = d0 + ty + r * 8;
        float v = tile[tx][ty + r * 8];
        __half h, l;
        split_half(v, h, l);
        size_t o = ob + (size_t)d * LL + i0 + tx;
        Vhi[o] = h;
        Vlo[o] = l;
    }
}

// ---------------------------------------------------------------------------
// Launch
// ---------------------------------------------------------------------------
extern "C" void kernel_launch(void* const* d_in, const int* in_sizes, int n_in,
                              void* d_out, int out_size)
{
    const float* q  = (const float*)d_in[0];
    const float* k  = (const float*)d_in[1];
    const float* v  = (const float*)d_in[2];
    const float* Wq = (const float*)d_in[3];
    const float* bq = (const float*)d_in[4];
    const float* Wk = (const float*)d_in[5];
    const float* bk = (const float*)d_in[6];
    const float* Wv = (const float*)d_in[7];
    const float* bv = (const float*)d_in[8];
    float* out = (float*)d_out;

    __half *qhi, *qlo, *khi, *klo, *vthi, *vtlo;
    float *vp, *S, *c, *pm, *ps;
    cudaGetSymbolAddress((void**)&qhi,  g_qhi);
    cudaGetSymbolAddress((void**)&qlo,  g_qlo);
    cudaGetSymbolAddress((void**)&khi,  g_khi);
    cudaGetSymbolAddress((void**)&klo,  g_klo);
    cudaGetSymbolAddress((void**)&vp,   g_vp);
    cudaGetSymbolAddress((void**)&S,    g_S);
    cudaGetSymbolAddress((void**)&c,    g_c);
    cudaGetSymbolAddress((void**)&pm,   g_pm);
    cudaGetSymbolAddress((void**)&ps,   g_ps);
    cudaGetSymbolAddress((void**)&vthi, g_vthi);
    cudaGetSymbolAddress((void**)&vtlo, g_vtlo);

    cudaFuncSetAttribute(score_mma,
                         cudaFuncAttributeMaxDynamicSharedMemorySize, MMA_DYN);
    cudaFuncSetAttribute(attn_out_fused,
                         cudaFuncAttributeMaxDynamicSharedMemorySize, AO2_DYN);

    // 1) Projections
    dim3 gProj(DD / TILE, (BB * LL) / TILE, 1);
    gemm_nt<<<gProj, 256>>>(q, Wq, bq, nullptr, qhi, qlo, DD, DD);
    gemm_nt<<<gProj, 256>>>(k, Wk, bk, nullptr, khi, klo, DD, DD);
    gemm_nt<<<gProj, 256>>>(v, Wv, bv, vp, nullptr, nullptr, DD, DD);

    // 2) V^T split
    v_split_t<<<dim3(DD / 32, LL / 32, BB), dim3(32, 8)>>>(vp, vthi, vtlo);

    // 3) Scores + per-tile softmax partials
    score_mma<<<dim3(LL / 128, LL / 128, BB), 256, MMA_DYN>>>(
        qhi, qlo, khi, klo, S, pm, ps, 0.0625f);

    // 4) Combine partials -> c
    combine<<<(BB * LL) / 8, dim3(32, 8)>>>(pm, ps, c);

    // 5) Fused output GEMM: one wave, S read once
    attn_out_fused<<<dim3(1, LL / 128, BB), 512, AO2_DYN>>>(
        S, c, vthi, vtlo, out);
}

// round 10
// speedup vs baseline: 1.2232x; 1.2232x over previous
#include <cuda_runtime.h>
#include <cuda_fp16.h>
#include <cstdint>

#define BB   4
#define LL   4096
#define DD   256
#define NJT  (LL / 128)

// ---------------------------------------------------------------------------
// Device scratch (allocation-free)
// ---------------------------------------------------------------------------
__device__ __align__(256) __half g_xqh[BB * LL * DD];   // split fp32 inputs
__device__ __align__(256) __half g_xql[BB * LL * DD];
__device__ __align__(256) __half g_xkh[BB * LL * DD];
__device__ __align__(256) __half g_xkl[BB * LL * DD];
__device__ __align__(256) __half g_xvh[BB * LL * DD];
__device__ __align__(256) __half g_xvl[BB * LL * DD];
__device__ __align__(256) __half g_wqh[DD * DD];        // split weights
__device__ __align__(256) __half g_wql[DD * DD];
__device__ __align__(256) __half g_wkh[DD * DD];
__device__ __align__(256) __half g_wkl[DD * DD];
__device__ __align__(256) __half g_wvh[DD * DD];
__device__ __align__(256) __half g_wvl[DD * DD];
__device__ __align__(256) __half g_qhi[BB * LL * DD];   // projected Q/K split
__device__ __align__(256) __half g_qlo[BB * LL * DD];
__device__ __align__(256) __half g_khi[BB * LL * DD];
__device__ __align__(256) __half g_klo[BB * LL * DD];
__device__ __align__(256) float  g_vp [BB * LL * DD];   // projected V fp32
__device__ __align__(256) float  g_S  [(size_t)BB * LL * LL];
__device__ __align__(256) float  g_c  [BB * LL];
__device__ __align__(256) float  g_pm [(size_t)BB * LL * NJT];
__device__ __align__(256) float  g_ps [(size_t)BB * LL * NJT];
__device__ __align__(256) __half g_vthi[BB * DD * LL];
__device__ __align__(256) __half g_vtlo[BB * DD * LL];

// ---------------------------------------------------------------------------
__device__ __forceinline__ void split_half(float x, __half& h, __half& l) {
    h = __float2half_rn(x);
    l = __float2half_rn(x - __half2float(h));
}

// ---------------------------------------------------------------------------
// Elementwise fp32 -> fp16 hi/lo split (inputs + weights)
// ---------------------------------------------------------------------------
__global__ void __launch_bounds__(256)
split2(const float* __restrict__ x, __half* __restrict__ h,
       __half* __restrict__ l, int n)
{
    int i = (blockIdx.x * 256 + threadIdx.x) * 4;
    if (i >= n) return;
    float4 v = *(const float4*)(x + i);
    __half h0, l0, h1, l1, h2, l2, h3, l3;
    split_half(v.x, h0, l0);
    split_half(v.y, h1, l1);
    split_half(v.z, h2, l2);
    split_half(v.w, h3, l3);
    __half2 hh01; hh01.x = h0; hh01.y = h1;
    __half2 hh23; hh23.x = h2; hh23.y = h3;
    __half2 ll01; ll01.x = l0; ll01.y = l1;
    __half2 ll23; ll23.x = l2; ll23.y = l3;
    *(__half2*)(h + i)     = hh01;
    *(__half2*)(h + i + 2) = hh23;
    *(__half2*)(l + i)     = ll01;
    *(__half2*)(l + i + 2) = ll23;
}

// ---------------------------------------------------------------------------
// mma.sync + ldmatrix + cp.async primitives
// ---------------------------------------------------------------------------
__device__ __forceinline__ void mma16816(float* d, const uint32_t* a, const uint32_t* b) {
    asm volatile(
        "mma.sync.aligned.m16n8k16.row.col.f32.f16.f16.f32 "
        "{%0,%1,%2,%3}, {%4,%5,%6,%7}, {%8,%9}, {%0,%1,%2,%3};"
        : "+f"(d[0]), "+f"(d[1]), "+f"(d[2]), "+f"(d[3])
        : "r"(a[0]), "r"(a[1]), "r"(a[2]), "r"(a[3]), "r"(b[0]), "r"(b[1]));
}
__device__ __forceinline__ void ldm_x4(uint32_t* r, uint32_t saddr) {
    asm volatile("ldmatrix.sync.aligned.m8n8.x4.shared.b16 {%0,%1,%2,%3}, [%4];"
                 : "=r"(r[0]), "=r"(r[1]), "=r"(r[2]), "=r"(r[3]) : "r"(saddr));
}
__device__ __forceinline__ uint32_t smem_u32p(const void* p) {
    uint32_t a;
    asm("{ .reg .u64 t; cvta.to.shared.u64 t, %1; cvt.u32.u64 %0, t; }"
        : "=r"(a) : "l"(p));
    return a;
}
__device__ __forceinline__ void cp_async16(uint32_t saddr, const void* g) {
    asm volatile("cp.async.cg.shared.global [%0], [%1], 16;"
                 :: "r"(saddr), "l"(g) : "memory");
}
#define CP_COMMIT()  asm volatile("cp.async.commit_group;" ::: "memory")
#define CP_WAIT1()   asm volatile("cp.async.wait_group 1;" ::: "memory")

#define SROW   40
#define PITCH  (SROW * 2)           // 80 B
#define OPSZ   (128 * PITCH)        // 10240 B
#define BUFSZ  (4 * OPSZ)
#define MMA_DYN (2 * BUFSZ)         // 81920 B

// One k16 step: ldmatrix fragment loads + 48 MMAs (verified in R8).
#define K16_STEP(ks, aoffh, aoffl, boffh, boffl)                               \
    do {                                                                       \
        uint32_t ah[4][4], al[4][4], bh[4][2], bl[4][2];                       \
        _Pragma("unroll")                                                      \
        for (int mt = 0; mt < 4; mt++) {                                       \
            uint32_t ra = (uint32_t)(wm * 64 + mt * 16 + lar) * PITCH          \
                        + ((ks) + lac) * 2;                                    \
            ldm_x4(ah[mt], (aoffh) + ra);                                      \
            ldm_x4(al[mt], (aoffl) + ra);                                      \
        }                                                                      \
        _Pragma("unroll")                                                      \
        for (int pp = 0; pp < 2; pp++) {                                       \
            uint32_t rb = (uint32_t)(wn * 32 + pp * 16 + lbr) * PITCH          \
                        + ((ks) + lbc) * 2;                                    \
            uint32_t tb[4];                                                    \
            ldm_x4(tb, (boffh) + rb);                                          \
            bh[2 * pp][0] = tb[0]; bh[2 * pp][1] = tb[1];                      \
            bh[2 * pp + 1][0] = tb[2]; bh[2 * pp + 1][1] = tb[3];              \
            ldm_x4(tb, (boffl) + rb);                                          \
            bl[2 * pp][0] = tb[0]; bl[2 * pp][1] = tb[1];                      \
            bl[2 * pp + 1][0] = tb[2]; bl[2 * pp + 1][1] = tb[3];              \
        }                                                                      \
        _Pragma("unroll")                                                      \
        for (int mt = 0; mt < 4; mt++)                                         \
            _Pragma("unroll")                                                  \
            for (int nt = 0; nt < 4; nt++) {                                   \
                mma16816(acc[mt][nt], ah[mt], bh[nt]);                         \
                mma16816(acc[mt][nt], ah[mt], bl[nt]);                         \
                mma16816(acc[mt][nt], al[mt], bh[nt]);                         \
            }                                                                  \
    } while (0)

// ---------------------------------------------------------------------------
// Projection GEMM on tensor cores:
//   Y[M,256] = (Xh+Xl)[M,256] @ (Wh+Wl)[256,256]^T + bias
// Output: fp32 (Cf) or fp16 hi/lo split (Oh/Ol).
// ---------------------------------------------------------------------------
__global__ void __launch_bounds__(256, 2)
proj_mma(const __half* __restrict__ Xh, const __half* __restrict__ Xl,
         const __half* __restrict__ Wh, const __half* __restrict__ Wl,
         const float* __restrict__ bias, float* __restrict__ Cf,
         __half* __restrict__ Oh, __half* __restrict__ Ol)
{
    extern __shared__ __align__(16) char dyn[];
    const uint32_t su = smem_u32p(dyn);

    const int t = threadIdx.x;
    const int wid = t >> 5, lane = t & 31;
    const int wm = wid >> 2;
    const int wn = wid & 3;
    const int fr = lane >> 2;
    const int fc = (lane & 3) * 2;
    const int lar = (lane & 7) + ((lane >> 3) & 1) * 8;
    const int lac = (lane >> 4) * 8;
    const int lbr = (lane & 7) + (lane >> 4) * 8;
    const int lbc = ((lane >> 3) & 1) * 8;

    const int m0 = blockIdx.y * 128;
    const int n0 = blockIdx.x * 128;

    float acc[4][4][4];
#pragma unroll
    for (int i = 0; i < 4; i++)
#pragma unroll
        for (int j = 0; j < 4; j++)
#pragma unroll
            for (int e = 0; e < 4; e++) acc[i][j][e] = 0.0f;

    const int srow = t >> 2;
    const int sq   = (t & 3) * 8;

    auto stage = [&](int b, int k0) {
        const uint32_t base = su + b * BUFSZ;
#pragma unroll
        for (int it = 0; it < 2; it++) {
            int row = srow + 64 * it;
            uint32_t so = base + row * PITCH + sq * 2;
            size_t ea = (size_t)(m0 + row) * DD + k0 + sq;
            size_t eb = (size_t)(n0 + row) * DD + k0 + sq;
            cp_async16(so + 0 * OPSZ, Xh + ea);
            cp_async16(so + 1 * OPSZ, Xl + ea);
            cp_async16(so + 2 * OPSZ, Wh + eb);
            cp_async16(so + 3 * OPSZ, Wl + eb);
        }
    };

    const int nchunks = DD >> 5;          // 8
    stage(0, 0);
    CP_COMMIT();

    for (int kc = 0; kc < nchunks; kc++) {
        if (kc + 1 < nchunks) stage((kc + 1) & 1, (kc + 1) << 5);
        CP_COMMIT();
        CP_WAIT1();
        __syncthreads();

        const uint32_t bb = su + (kc & 1) * BUFSZ;
        K16_STEP(0,  bb, bb + OPSZ, bb + 2 * OPSZ, bb + 3 * OPSZ);
        K16_STEP(16, bb, bb + OPSZ, bb + 2 * OPSZ, bb + 3 * OPSZ);
        __syncthreads();
    }

#pragma unroll
    for (int mt = 0; mt < 4; mt++) {
#pragma unroll
        for (int h = 0; h < 2; h++) {
            int row = m0 + wm * 64 + mt * 16 + fr + 8 * h;
            size_t rowoff = (size_t)row * DD;
#pragma unroll
            for (int nt = 0; nt < 4; nt++) {
                int col = n0 + wn * 32 + nt * 8 + fc;
                float vx = acc[mt][nt][2 * h]     + bias[col];
                float vy = acc[mt][nt][2 * h + 1] + bias[col + 1];
                if (Oh) {
                    __half h0, l0, h1, l1;
                    split_half(vx, h0, l0);
                    split_half(vy, h1, l1);
                    __half2 hh; hh.x = h0; hh.y = h1;
                    __half2 ll; ll.x = l0; ll.y = l1;
                    *(__half2*)(Oh + rowoff + col) = hh;
                    *(__half2*)(Ol + rowoff + col) = ll;
                } else {
                    float2 vv; vv.x = vx; vv.y = vy;
                    *(float2*)(Cf + rowoff + col) = vv;
                }
            }
        }
    }
}

// ---------------------------------------------------------------------------
// Score GEMM + per-tile softmax partials
// ---------------------------------------------------------------------------
__global__ void __launch_bounds__(256, 2)
score_mma(const __half* __restrict__ Ahg, const __half* __restrict__ Alg,
          const __half* __restrict__ Bhg, const __half* __restrict__ Blg,
          float* __restrict__ C, float* __restrict__ pm, float* __restrict__ ps,
          float scale)
{
    extern __shared__ __align__(16) char dyn[];
    const uint32_t su = smem_u32p(dyn);
    __shared__ float redm[128][4];
    __shared__ float redl[128][4];
    __shared__ float redmax[128];

    const int t = threadIdx.x;
    const int wid = t >> 5, lane = t & 31;
    const int wm = wid >> 2;
    const int wn = wid & 3;
    const int fr = lane >> 2;
    const int fc = (lane & 3) * 2;
    const int lar = (lane & 7) + ((lane >> 3) & 1) * 8;
    const int lac = (lane >> 4) * 8;
    const int lbr = (lane & 7) + (lane >> 4) * 8;
    const int lbc = ((lane >> 3) & 1) * 8;

    const size_t zqk = (size_t)LL * DD;
    Ahg += (size_t)blockIdx.z * zqk;  Alg += (size_t)blockIdx.z * zqk;
    Bhg += (size_t)blockIdx.z * zqk;  Blg += (size_t)blockIdx.z * zqk;
    C   += (size_t)blockIdx.z * LL * LL;
    const int m0 = blockIdx.y * 128;
    const int n0 = blockIdx.x * 128;

    float acc[4][4][4];
#pragma unroll
    for (int i = 0; i < 4; i++)
#pragma unroll
        for (int j = 0; j < 4; j++)
#pragma unroll
            for (int e = 0; e < 4; e++) acc[i][j][e] = 0.0f;

    const int srow = t >> 2;
    const int sq   = (t & 3) * 8;

    auto stage = [&](int b, int k0) {
        const uint32_t base = su + b * BUFSZ;
#pragma unroll
        for (int it = 0; it < 2; it++) {
            int row = srow + 64 * it;
            uint32_t so = base + row * PITCH + sq * 2;
            size_t ea = (size_t)(m0 + row) * DD + k0 + sq;
            size_t eb = (size_t)(n0 + row) * DD + k0 + sq;
            cp_async16(so + 0 * OPSZ, Ahg + ea);
            cp_async16(so + 1 * OPSZ, Alg + ea);
            cp_async16(so + 2 * OPSZ, Bhg + eb);
            cp_async16(so + 3 * OPSZ, Blg + eb);
        }
    };

    const int nchunks = DD >> 5;
    stage(0, 0);
    CP_COMMIT();

    for (int kc = 0; kc < nchunks; kc++) {
        if (kc + 1 < nchunks) stage((kc + 1) & 1, (kc + 1) << 5);
        CP_COMMIT();
        CP_WAIT1();
        __syncthreads();

        const uint32_t bb = su + (kc & 1) * BUFSZ;
        K16_STEP(0,  bb, bb + OPSZ, bb + 2 * OPSZ, bb + 3 * OPSZ);
        K16_STEP(16, bb, bb + OPSZ, bb + 2 * OPSZ, bb + 3 * OPSZ);
        __syncthreads();
    }

#pragma unroll
    for (int mt = 0; mt < 4; mt++) {
        int row = m0 + wm * 64 + mt * 16 + fr;
#pragma unroll
        for (int nt = 0; nt < 4; nt++) {
            int col = n0 + wn * 32 + nt * 8 + fc;
            float2 v0, v1;
            v0.x = acc[mt][nt][0] * scale;
            v0.y = acc[mt][nt][1] * scale;
            v1.x = acc[mt][nt][2] * scale;
            v1.y = acc[mt][nt][3] * scale;
            *(float2*)(C + (size_t)row * LL + col)       = v0;
            *(float2*)(C + (size_t)(row + 8) * LL + col) = v1;
        }
    }

    float rm[4][2];
#pragma unroll
    for (int mt = 0; mt < 4; mt++)
#pragma unroll
        for (int h = 0; h < 2; h++) {
            float m = -3.0e38f;
#pragma unroll
            for (int nt = 0; nt < 4; nt++) {
                m = fmaxf(m, acc[mt][nt][2 * h]     * scale);
                m = fmaxf(m, acc[mt][nt][2 * h + 1] * scale);
            }
#pragma unroll
            for (int o = 1; o <= 2; o <<= 1)
                m = fmaxf(m, __shfl_xor_sync(0xffffffffu, m, o));
            rm[mt][h] = m;
        }
    if ((lane & 3) == 0) {
#pragma unroll
        for (int mt = 0; mt < 4; mt++)
#pragma unroll
            for (int h = 0; h < 2; h++)
                redm[wm * 64 + mt * 16 + fr + 8 * h][wn] = rm[mt][h];
    }
    __syncthreads();
    if (t < 128)
        redmax[t] = fmaxf(fmaxf(redm[t][0], redm[t][1]),
                          fmaxf(redm[t][2], redm[t][3]));
    __syncthreads();
#pragma unroll
    for (int mt = 0; mt < 4; mt++)
#pragma unroll
        for (int h = 0; h < 2; h++) {
            int r = wm * 64 + mt * 16 + fr + 8 * h;
            float rmx = redmax[r];
            float s = 0.0f;
#pragma unroll
            for (int nt = 0; nt < 4; nt++) {
                s += __expf(acc[mt][nt][2 * h]     * scale - rmx);
                s += __expf(acc[mt][nt][2 * h + 1] * scale - rmx);
            }
#pragma unroll
            for (int o = 1; o <= 2; o <<= 1)
                s += __shfl_xor_sync(0xffffffffu, s, o);
            if ((lane & 3) == 0) redl[r][wn] = s;
        }
    __syncthreads();
    if (t < 128) {
        float sum = redl[t][0] + redl[t][1] + redl[t][2] + redl[t][3];
        size_t o = ((size_t)blockIdx.z * LL + m0 + t) * NJT + blockIdx.x;
        pm[o] = redmax[t];
        ps[o] = sum;
    }
}

// ---------------------------------------------------------------------------
// Combine partials
// ---------------------------------------------------------------------------
__global__ void __launch_bounds__(256)
combine(const float* __restrict__ pm, const float* __restrict__ ps,
        float* __restrict__ c)
{
    const int row = blockIdx.x * 8 + threadIdx.y;
    const int tx  = threadIdx.x;
    size_t base = (size_t)row * NJT + tx;
    float m = pm[base];
    float l = ps[base];
    float M = m;
#pragma unroll
    for (int o = 16; o > 0; o >>= 1)
        M = fmaxf(M, __shfl_xor_sync(0xffffffffu, M, o));
    float s = l * __expf(m - M);
#pragma unroll
    for (int o = 16; o > 0; o >>= 1)
        s += __shfl_xor_sync(0xffffffffu, s, o);
    if (tx == 0) c[row] = M + __logf(s);
}

// ---------------------------------------------------------------------------
// Fused output GEMM (R8 shape: 128j x 128d, 256 threads)
// ---------------------------------------------------------------------------
#define AOS_SSZ  (32 * 132 * 4)
#define AOS_AH   (2 * AOS_SSZ)
#define AOS_AL   (AOS_AH + OPSZ)
#define AOS_B0   (AOS_AL + OPSZ)
#define AOS_DYN  (AOS_B0 + 2 * 2 * OPSZ)

__global__ void __launch_bounds__(256, 2)
attn_out_fused(const float* __restrict__ S, const float* __restrict__ cst,
               const __half* __restrict__ Vth, const __half* __restrict__ Vtl,
               float* __restrict__ out)
{
    extern __shared__ __align__(16) char dyn[];
    __shared__ float sc[32];
    const uint32_t su = smem_u32p(dyn);

    const int t = threadIdx.x;
    const int wid = t >> 5, lane = t & 31;
    const int wm = wid >> 2;
    const int wn = wid & 3;
    const int fr = lane >> 2;
    const int fc = (lane & 3) * 2;
    const int lar = (lane & 7) + ((lane >> 3) & 1) * 8;
    const int lac = (lane >> 4) * 8;
    const int lbr = (lane & 7) + (lane >> 4) * 8;
    const int lbc = ((lane >> 3) & 1) * 8;

    const int b = blockIdx.z;
    const float* Sb  = S   + (size_t)b * LL * LL;
    const float* cb  = cst + (size_t)b * LL;
    const __half* Vh = Vth + (size_t)b * DD * LL;
    const __half* Vl = Vtl + (size_t)b * DD * LL;
    float* Ob = out + (size_t)b * LL * DD;

    const int j0 = blockIdx.y * 128;
    const int d0 = blockIdx.x * 128;

    float acc[4][4][4];
#pragma unroll
    for (int i = 0; i < 4; i++)
#pragma unroll
        for (int j = 0; j < 4; j++)
#pragma unroll
            for (int e = 0; e < 4; e++) acc[i][j][e] = 0.0f;

    const int srow = t >> 2;
    const int sq   = (t & 3) * 8;

    auto stageB = [&](int buf, int i0) {
        const uint32_t base = su + AOS_B0 + buf * (2 * OPSZ);
#pragma unroll
        for (int it = 0; it < 2; it++) {
            int row = srow + 64 * it;
            uint32_t so = base + row * PITCH + sq * 2;
            size_t e = (size_t)(d0 + row) * LL + i0 + sq;
            cp_async16(so,        Vh + e);
            cp_async16(so + OPSZ, Vl + e);
        }
    };
    auto stageS = [&](int buf, int i0) {
        const uint32_t base = su + buf * AOS_SSZ;
#pragma unroll
        for (int u = 0; u < 4; u++) {
            int idx = t + 256 * u;
            int row = idx >> 5;
            int c4  = (idx & 31) * 4;
            cp_async16(base + row * 528 + c4 * 4,
                       Sb + (size_t)(i0 + row) * LL + j0 + c4);
        }
    };

    const int nchunks = LL >> 5;       // 128
    stageB(0, 0);
    stageS(0, 0);
    CP_COMMIT();

    const int jl = t & 127;
    const int ih = (t >> 7) * 16;

    for (int kc = 0; kc < nchunks; kc++) {
        const int i0 = kc << 5;
        if (kc + 1 < nchunks) {
            stageB((kc + 1) & 1, i0 + 32);
            stageS((kc + 1) & 1, i0 + 32);
        }
        CP_COMMIT();
        CP_WAIT1();
        if (t < 32) sc[t] = cb[i0 + t];
        __syncthreads();

        // ---- transform: exp + split + transpose into sAh/sAl [j][i] ----
        {
            const float* sSp = (const float*)(dyn + (kc & 1) * AOS_SSZ);
            __half2 hb[8], lb[8];
#pragma unroll
            for (int ii = 0; ii < 16; ii += 2) {
                float s0 = sSp[(ih + ii)     * 132 + jl];
                float s1 = sSp[(ih + ii + 1) * 132 + jl];
                float p0 = __expf(s0 - sc[ih + ii]);
                float p1 = __expf(s1 - sc[ih + ii + 1]);
                __half h0 = __float2half_rn(p0);
                __half h1 = __float2half_rn(p1);
                __half l0 = __float2half_rn(p0 - __half2float(h0));
                __half l1 = __float2half_rn(p1 - __half2float(h1));
                hb[ii >> 1] = __halves2half2(h0, h1);
                lb[ii >> 1] = __halves2half2(l0, l1);
            }
            char* ah = dyn + AOS_AH + jl * PITCH + ih * 2;
            char* al = dyn + AOS_AL + jl * PITCH + ih * 2;
            *(uint4*)(ah)      = *(uint4*)&hb[0];
            *(uint4*)(ah + 16) = *(uint4*)&hb[4];
            *(uint4*)(al)      = *(uint4*)&lb[0];
            *(uint4*)(al + 16) = *(uint4*)&lb[4];
        }
        __syncthreads();

        const uint32_t aoh = su + AOS_AH;
        const uint32_t aol = su + AOS_AL;
        const uint32_t bbh = su + AOS_B0 + (kc & 1) * (2 * OPSZ);
        const uint32_t bbl = bbh + OPSZ;
        K16_STEP(0,  aoh, aol, bbh, bbl);
        K16_STEP(16, aoh, aol, bbh, bbl);
        __syncthreads();
    }

#pragma unroll
    for (int mt = 0; mt < 4; mt++) {
        int row = j0 + wm * 64 + mt * 16 + fr;
#pragma unroll
        for (int nt = 0; nt < 4; nt++) {
            int col = d0 + wn * 32 + nt * 8 + fc;
            float2 v0, v1;
            v0.x = acc[mt][nt][0];
            v0.y = acc[mt][nt][1];
            v1.x = acc[mt][nt][2];
            v1.y = acc[mt][nt][3];
            *(float2*)(Ob + (size_t)row * DD + col)       = v0;
            *(float2*)(Ob + (size_t)(row + 8) * DD + col) = v1;
        }
    }
}

// ---------------------------------------------------------------------------
// V^T build
// ---------------------------------------------------------------------------
__global__ void __launch_bounds__(256)
v_split_t(const float* __restrict__ V,
          __half* __restrict__ Vhi, __half* __restrict__ Vlo)
{
    const int b = blockIdx.z;
    const float* Vb = V + (size_t)b * LL * DD;
    __shared__ float tile[32][33];
    const int tx = threadIdx.x, ty = threadIdx.y;
    const int d0 = blockIdx.x * 32, i0 = blockIdx.y * 32;

#pragma unroll
    for (int r = 0; r < 4; r++) {
        int i = i0 + ty + r * 8;
        tile[ty + r * 8][tx] = Vb[(size_t)i * DD + d0 + tx];
    }
    __syncthreads();
    const size_t ob = (size_t)b * DD * LL;
#pragma unroll
    for (int r = 0; r < 4; r++) {
        int d = d0 + ty + r * 8;
        float v = tile[tx][ty + r * 8];
        __half h, l;
        split_half(v, h, l);
        size_t o = ob + (size_t)d * LL + i0 + tx;
        Vhi[o] = h;
        Vlo[o] = l;
    }
}

// ---------------------------------------------------------------------------
// Launch
// ---------------------------------------------------------------------------
extern "C" void kernel_launch(void* const* d_in, const int* in_sizes, int n_in,
                              void* d_out, int out_size)
{
    const float* q  = (const float*)d_in[0];
    const float* k  = (const float*)d_in[1];
    const float* v  = (const float*)d_in[2];
    const float* Wq = (const float*)d_in[3];
    const float* bq = (const float*)d_in[4];
    const float* Wk = (const float*)d_in[5];
    const float* bk = (const float*)d_in[6];
    const float* Wv = (const float*)d_in[7];
    const float* bv = (const float*)d_in[8];
    float* out = (float*)d_out;

    __half *xqh, *xql, *xkh, *xkl, *xvh, *xvl;
    __half *wqh, *wql, *wkh, *wkl, *wvh, *wvl;
    __half *qhi, *qlo, *khi, *klo, *vthi, *vtlo;
    float *vp, *S, *c, *pm, *ps;
    cudaGetSymbolAddress((void**)&xqh,  g_xqh);
    cudaGetSymbolAddress((void**)&xql,  g_xql);
    cudaGetSymbolAddress((void**)&xkh,  g_xkh);
    cudaGetSymbolAddress((void**)&xkl,  g_xkl);
    cudaGetSymbolAddress((void**)&xvh,  g_xvh);
    cudaGetSymbolAddress((void**)&xvl,  g_xvl);
    cudaGetSymbolAddress((void**)&wqh,  g_wqh);
    cudaGetSymbolAddress((void**)&wql,  g_wql);
    cudaGetSymbolAddress((void**)&wkh,  g_wkh);
    cudaGetSymbolAddress((void**)&wkl,  g_wkl);
    cudaGetSymbolAddress((void**)&wvh,  g_wvh);
    cudaGetSymbolAddress((void**)&wvl,  g_wvl);
    cudaGetSymbolAddress((void**)&qhi,  g_qhi);
    cudaGetSymbolAddress((void**)&qlo,  g_qlo);
    cudaGetSymbolAddress((void**)&khi,  g_khi);
    cudaGetSymbolAddress((void**)&klo,  g_klo);
    cudaGetSymbolAddress((void**)&vp,   g_vp);
    cudaGetSymbolAddress((void**)&S,    g_S);
    cudaGetSymbolAddress((void**)&c,    g_c);
    cudaGetSymbolAddress((void**)&pm,   g_pm);
    cudaGetSymbolAddress((void**)&ps,   g_ps);
    cudaGetSymbolAddress((void**)&vthi, g_vthi);
    cudaGetSymbolAddress((void**)&vtlo, g_vtlo);

    cudaFuncSetAttribute(proj_mma,
                         cudaFuncAttributeMaxDynamicSharedMemorySize, MMA_DYN);
    cudaFuncSetAttribute(score_mma,
                         cudaFuncAttributeMaxDynamicSharedMemorySize, MMA_DYN);
    cudaFuncSetAttribute(attn_out_fused,
                         cudaFuncAttributeMaxDynamicSharedMemorySize, AOS_DYN);

    const int NX = BB * LL * DD;   // 4,194,304
    const int NW = DD * DD;        // 65,536

    // 0) Split inputs + weights to fp16 hi/lo
    split2<<<NX / 1024, 256>>>(q, xqh, xql, NX);
    split2<<<NX / 1024, 256>>>(k, xkh, xkl, NX);
    split2<<<NX / 1024, 256>>>(v, xvh, xvl, NX);
    split2<<<NW / 1024, 256>>>(Wq, wqh, wql, NW);
    split2<<<NW / 1024, 256>>>(Wk, wkh, wkl, NW);
    split2<<<NW / 1024, 256>>>(Wv, wvh, wvl, NW);

    // 1) Projections on tensor cores
    dim3 gProj(DD / 128, (BB * LL) / 128, 1);
    proj_mma<<<gProj, 256, MMA_DYN>>>(xqh, xql, wqh, wql, bq, nullptr, qhi, qlo);
    proj_mma<<<gProj, 256, MMA_DYN>>>(xkh, xkl, wkh, wkl, bk, nullptr, khi, klo);
    proj_mma<<<gProj, 256, MMA_DYN>>>(xvh, xvl, wvh, wvl, bv, vp, nullptr, nullptr);

    // 2) V^T split
    v_split_t<<<dim3(DD / 32, LL / 32, BB), dim3(32, 8)>>>(vp, vthi, vtlo);

    // 3) Scores + per-tile softmax partials
    score_mma<<<dim3(LL / 128, LL / 128, BB), 256, MMA_DYN>>>(
        qhi, qlo, khi, klo, S, pm, ps, 0.0625f);

    // 4) Combine partials -> c
    combine<<<(BB * LL) / 8, dim3(32, 8)>>>(pm, ps, c);

    // 5) Fused output GEMM (R8 shape)
    attn_out_fused<<<dim3(DD / 128, LL / 128, BB), 256, AOS_DYN>>>(
        S, c, vthi, vtlo, out);
}

// round 11
// speedup vs baseline: 1.3153x; 1.0753x over previous
#include <cuda_runtime.h>
#include <cuda_fp16.h>
#include <cstdint>

#define BB   4
#define LL   4096
#define DD   256
#define NJT  (LL / 128)

// ---------------------------------------------------------------------------
// Device scratch (allocation-free)
// ---------------------------------------------------------------------------
__device__ __align__(256) __half g_xqh[BB * LL * DD];
__device__ __align__(256) __half g_xql[BB * LL * DD];
__device__ __align__(256) __half g_xkh[BB * LL * DD];
__device__ __align__(256) __half g_xkl[BB * LL * DD];
__device__ __align__(256) __half g_xvh[BB * LL * DD];
__device__ __align__(256) __half g_xvl[BB * LL * DD];
__device__ __align__(256) __half g_wqh[DD * DD];
__device__ __align__(256) __half g_wql[DD * DD];
__device__ __align__(256) __half g_wkh[DD * DD];
__device__ __align__(256) __half g_wkl[DD * DD];
__device__ __align__(256) __half g_wvh[DD * DD];
__device__ __align__(256) __half g_wvl[DD * DD];
__device__ __align__(256) __half g_qhi[BB * LL * DD];
__device__ __align__(256) __half g_qlo[BB * LL * DD];
__device__ __align__(256) __half g_khi[BB * LL * DD];
__device__ __align__(256) __half g_klo[BB * LL * DD];
__device__ __align__(256) float  g_vp [BB * LL * DD];
__device__ __align__(256) float  g_S  [(size_t)BB * LL * LL];
__device__ __align__(256) float  g_c  [BB * LL];
__device__ __align__(256) float  g_pm [(size_t)BB * LL * NJT];
__device__ __align__(256) float  g_ps [(size_t)BB * LL * NJT];
__device__ __align__(256) __half g_vthi[BB * DD * LL];
__device__ __align__(256) __half g_vtlo[BB * DD * LL];

// ---------------------------------------------------------------------------
__device__ __forceinline__ void split_half(float x, __half& h, __half& l) {
    h = __float2half_rn(x);
    l = __float2half_rn(x - __half2float(h));
}

// ---------------------------------------------------------------------------
// Elementwise fp32 -> fp16 hi/lo split
// ---------------------------------------------------------------------------
__global__ void __launch_bounds__(256)
split2(const float* __restrict__ x, __half* __restrict__ h,
       __half* __restrict__ l, int n)
{
    int i = (blockIdx.x * 256 + threadIdx.x) * 4;
    if (i >= n) return;
    float4 v = *(const float4*)(x + i);
    __half h0, l0, h1, l1, h2, l2, h3, l3;
    split_half(v.x, h0, l0);
    split_half(v.y, h1, l1);
    split_half(v.z, h2, l2);
    split_half(v.w, h3, l3);
    __half2 hh01; hh01.x = h0; hh01.y = h1;
    __half2 hh23; hh23.x = h2; hh23.y = h3;
    __half2 ll01; ll01.x = l0; ll01.y = l1;
    __half2 ll23; ll23.x = l2; ll23.y = l3;
    *(__half2*)(h + i)     = hh01;
    *(__half2*)(h + i + 2) = hh23;
    *(__half2*)(l + i)     = ll01;
    *(__half2*)(l + i + 2) = ll23;
}

// ---------------------------------------------------------------------------
// mma.sync + ldmatrix + cp.async primitives
// ---------------------------------------------------------------------------
__device__ __forceinline__ void mma16816(float* d, const uint32_t* a, const uint32_t* b) {
    asm volatile(
        "mma.sync.aligned.m16n8k16.row.col.f32.f16.f16.f32 "
        "{%0,%1,%2,%3}, {%4,%5,%6,%7}, {%8,%9}, {%0,%1,%2,%3};"
        : "+f"(d[0]), "+f"(d[1]), "+f"(d[2]), "+f"(d[3])
        : "r"(a[0]), "r"(a[1]), "r"(a[2]), "r"(a[3]), "r"(b[0]), "r"(b[1]));
}
__device__ __forceinline__ void ldm_x4(uint32_t* r, uint32_t saddr) {
    asm volatile("ldmatrix.sync.aligned.m8n8.x4.shared.b16 {%0,%1,%2,%3}, [%4];"
                 : "=r"(r[0]), "=r"(r[1]), "=r"(r[2]), "=r"(r[3]) : "r"(saddr));
}
__device__ __forceinline__ uint32_t smem_u32p(const void* p) {
    uint32_t a;
    asm("{ .reg .u64 t; cvta.to.shared.u64 t, %1; cvt.u32.u64 %0, t; }"
        : "=r"(a) : "l"(p));
    return a;
}
__device__ __forceinline__ void cp_async16(uint32_t saddr, const void* g) {
    asm volatile("cp.async.cg.shared.global [%0], [%1], 16;"
                 :: "r"(saddr), "l"(g) : "memory");
}
#define CP_COMMIT()  asm volatile("cp.async.commit_group;" ::: "memory")
#define CP_WAIT1()   asm volatile("cp.async.wait_group 1;" ::: "memory")

#define SROW   40
#define PITCH  (SROW * 2)           // 80 B
#define OPSZ   (128 * PITCH)        // 10240 B
#define BUFSZ  (4 * OPSZ)
#define MMA_DYN (2 * BUFSZ)         // 81920 B

// One 3-term k16 step (projections + score)
#define K16_STEP(ks, aoffh, aoffl, boffh, boffl)                               \
    do {                                                                       \
        uint32_t ah[4][4], al[4][4], bh[4][2], bl[4][2];                       \
        _Pragma("unroll")                                                      \
        for (int mt = 0; mt < 4; mt++) {                                       \
            uint32_t ra = (uint32_t)(wm * 64 + mt * 16 + lar) * PITCH          \
                        + ((ks) + lac) * 2;                                    \
            ldm_x4(ah[mt], (aoffh) + ra);                                      \
            ldm_x4(al[mt], (aoffl) + ra);                                      \
        }                                                                      \
        _Pragma("unroll")                                                      \
        for (int pp = 0; pp < 2; pp++) {                                       \
            uint32_t rb = (uint32_t)(wn * 32 + pp * 16 + lbr) * PITCH          \
                        + ((ks) + lbc) * 2;                                    \
            uint32_t tb[4];                                                    \
            ldm_x4(tb, (boffh) + rb);                                          \
            bh[2 * pp][0] = tb[0]; bh[2 * pp][1] = tb[1];                      \
            bh[2 * pp + 1][0] = tb[2]; bh[2 * pp + 1][1] = tb[3];              \
            ldm_x4(tb, (boffl) + rb);                                          \
            bl[2 * pp][0] = tb[0]; bl[2 * pp][1] = tb[1];                      \
            bl[2 * pp + 1][0] = tb[2]; bl[2 * pp + 1][1] = tb[3];              \
        }                                                                      \
        _Pragma("unroll")                                                      \
        for (int mt = 0; mt < 4; mt++)                                         \
            _Pragma("unroll")                                                  \
            for (int nt = 0; nt < 4; nt++) {                                   \
                mma16816(acc[mt][nt], ah[mt], bh[nt]);                         \
                mma16816(acc[mt][nt], ah[mt], bl[nt]);                         \
                mma16816(acc[mt][nt], al[mt], bh[nt]);                         \
            }                                                                  \
    } while (0)

// ---------------------------------------------------------------------------
// Projection GEMM on tensor cores
// ---------------------------------------------------------------------------
__global__ void __launch_bounds__(256, 2)
proj_mma(const __half* __restrict__ Xh, const __half* __restrict__ Xl,
         const __half* __restrict__ Wh, const __half* __restrict__ Wl,
         const float* __restrict__ bias, float* __restrict__ Cf,
         __half* __restrict__ Oh, __half* __restrict__ Ol)
{
    extern __shared__ __align__(16) char dyn[];
    const uint32_t su = smem_u32p(dyn);

    const int t = threadIdx.x;
    const int wid = t >> 5, lane = t & 31;
    const int wm = wid >> 2;
    const int wn = wid & 3;
    const int fr = lane >> 2;
    const int fc = (lane & 3) * 2;
    const int lar = (lane & 7) + ((lane >> 3) & 1) * 8;
    const int lac = (lane >> 4) * 8;
    const int lbr = (lane & 7) + (lane >> 4) * 8;
    const int lbc = ((lane >> 3) & 1) * 8;

    const int m0 = blockIdx.y * 128;
    const int n0 = blockIdx.x * 128;

    float acc[4][4][4];
#pragma unroll
    for (int i = 0; i < 4; i++)
#pragma unroll
        for (int j = 0; j < 4; j++)
#pragma unroll
            for (int e = 0; e < 4; e++) acc[i][j][e] = 0.0f;

    const int srow = t >> 2;
    const int sq   = (t & 3) * 8;

    auto stage = [&](int b, int k0) {
        const uint32_t base = su + b * BUFSZ;
#pragma unroll
        for (int it = 0; it < 2; it++) {
            int row = srow + 64 * it;
            uint32_t so = base + row * PITCH + sq * 2;
            size_t ea = (size_t)(m0 + row) * DD + k0 + sq;
            size_t eb = (size_t)(n0 + row) * DD + k0 + sq;
            cp_async16(so + 0 * OPSZ, Xh + ea);
            cp_async16(so + 1 * OPSZ, Xl + ea);
            cp_async16(so + 2 * OPSZ, Wh + eb);
            cp_async16(so + 3 * OPSZ, Wl + eb);
        }
    };

    const int nchunks = DD >> 5;
    stage(0, 0);
    CP_COMMIT();

    for (int kc = 0; kc < nchunks; kc++) {
        if (kc + 1 < nchunks) stage((kc + 1) & 1, (kc + 1) << 5);
        CP_COMMIT();
        CP_WAIT1();
        __syncthreads();

        const uint32_t bb = su + (kc & 1) * BUFSZ;
        K16_STEP(0,  bb, bb + OPSZ, bb + 2 * OPSZ, bb + 3 * OPSZ);
        K16_STEP(16, bb, bb + OPSZ, bb + 2 * OPSZ, bb + 3 * OPSZ);
        __syncthreads();
    }

#pragma unroll
    for (int mt = 0; mt < 4; mt++) {
#pragma unroll
        for (int h = 0; h < 2; h++) {
            int row = m0 + wm * 64 + mt * 16 + fr + 8 * h;
            size_t rowoff = (size_t)row * DD;
#pragma unroll
            for (int nt = 0; nt < 4; nt++) {
                int col = n0 + wn * 32 + nt * 8 + fc;
                float vx = acc[mt][nt][2 * h]     + bias[col];
                float vy = acc[mt][nt][2 * h + 1] + bias[col + 1];
                if (Oh) {
                    __half h0, l0, h1, l1;
                    split_half(vx, h0, l0);
                    split_half(vy, h1, l1);
                    __half2 hh; hh.x = h0; hh.y = h1;
                    __half2 ll; ll.x = l0; ll.y = l1;
                    *(__half2*)(Oh + rowoff + col) = hh;
                    *(__half2*)(Ol + rowoff + col) = ll;
                } else {
                    float2 vv; vv.x = vx; vv.y = vy;
                    *(float2*)(Cf + rowoff + col) = vv;
                }
            }
        }
    }
}

// ---------------------------------------------------------------------------
// Score GEMM + per-tile softmax partials
// ---------------------------------------------------------------------------
__global__ void __launch_bounds__(256, 2)
score_mma(const __half* __restrict__ Ahg, const __half* __restrict__ Alg,
          const __half* __restrict__ Bhg, const __half* __restrict__ Blg,
          float* __restrict__ C, float* __restrict__ pm, float* __restrict__ ps,
          float scale)
{
    extern __shared__ __align__(16) char dyn[];
    const uint32_t su = smem_u32p(dyn);
    __shared__ float redm[128][4];
    __shared__ float redl[128][4];
    __shared__ float redmax[128];

    const int t = threadIdx.x;
    const int wid = t >> 5, lane = t & 31;
    const int wm = wid >> 2;
    const int wn = wid & 3;
    const int fr = lane >> 2;
    const int fc = (lane & 3) * 2;
    const int lar = (lane & 7) + ((lane >> 3) & 1) * 8;
    const int lac = (lane >> 4) * 8;
    const int lbr = (lane & 7) + (lane >> 4) * 8;
    const int lbc = ((lane >> 3) & 1) * 8;

    const size_t zqk = (size_t)LL * DD;
    Ahg += (size_t)blockIdx.z * zqk;  Alg += (size_t)blockIdx.z * zqk;
    Bhg += (size_t)blockIdx.z * zqk;  Blg += (size_t)blockIdx.z * zqk;
    C   += (size_t)blockIdx.z * LL * LL;
    const int m0 = blockIdx.y * 128;
    const int n0 = blockIdx.x * 128;

    float acc[4][4][4];
#pragma unroll
    for (int i = 0; i < 4; i++)
#pragma unroll
        for (int j = 0; j < 4; j++)
#pragma unroll
            for (int e = 0; e < 4; e++) acc[i][j][e] = 0.0f;

    const int srow = t >> 2;
    const int sq   = (t & 3) * 8;

    auto stage = [&](int b, int k0) {
        const uint32_t base = su + b * BUFSZ;
#pragma unroll
        for (int it = 0; it < 2; it++) {
            int row = srow + 64 * it;
            uint32_t so = base + row * PITCH + sq * 2;
            size_t ea = (size_t)(m0 + row) * DD + k0 + sq;
            size_t eb = (size_t)(n0 + row) * DD + k0 + sq;
            cp_async16(so + 0 * OPSZ, Ahg + ea);
            cp_async16(so + 1 * OPSZ, Alg + ea);
            cp_async16(so + 2 * OPSZ, Bhg + eb);
            cp_async16(so + 3 * OPSZ, Blg + eb);
        }
    };

    const int nchunks = DD >> 5;
    stage(0, 0);
    CP_COMMIT();

    for (int kc = 0; kc < nchunks; kc++) {
        if (kc + 1 < nchunks) stage((kc + 1) & 1, (kc + 1) << 5);
        CP_COMMIT();
        CP_WAIT1();
        __syncthreads();

        const uint32_t bb = su + (kc & 1) * BUFSZ;
        K16_STEP(0,  bb, bb + OPSZ, bb + 2 * OPSZ, bb + 3 * OPSZ);
        K16_STEP(16, bb, bb + OPSZ, bb + 2 * OPSZ, bb + 3 * OPSZ);
        __syncthreads();
    }

#pragma unroll
    for (int mt = 0; mt < 4; mt++) {
        int row = m0 + wm * 64 + mt * 16 + fr;
#pragma unroll
        for (int nt = 0; nt < 4; nt++) {
            int col = n0 + wn * 32 + nt * 8 + fc;
            float2 v0, v1;
            v0.x = acc[mt][nt][0] * scale;
            v0.y = acc[mt][nt][1] * scale;
            v1.x = acc[mt][nt][2] * scale;
            v1.y = acc[mt][nt][3] * scale;
            *(float2*)(C + (size_t)row * LL + col)       = v0;
            *(float2*)(C + (size_t)(row + 8) * LL + col) = v1;
        }
    }

    float rm[4][2];
#pragma unroll
    for (int mt = 0; mt < 4; mt++)
#pragma unroll
        for (int h = 0; h < 2; h++) {
            float m = -3.0e38f;
#pragma unroll
            for (int nt = 0; nt < 4; nt++) {
                m = fmaxf(m, acc[mt][nt][2 * h]     * scale);
                m = fmaxf(m, acc[mt][nt][2 * h + 1] * scale);
            }
#pragma unroll
            for (int o = 1; o <= 2; o <<= 1)
                m = fmaxf(m, __shfl_xor_sync(0xffffffffu, m, o));
            rm[mt][h] = m;
        }
    if ((lane & 3) == 0) {
#pragma unroll
        for (int mt = 0; mt < 4; mt++)
#pragma unroll
            for (int h = 0; h < 2; h++)
                redm[wm * 64 + mt * 16 + fr + 8 * h][wn] = rm[mt][h];
    }
    __syncthreads();
    if (t < 128)
        redmax[t] = fmaxf(fmaxf(redm[t][0], redm[t][1]),
                          fmaxf(redm[t][2], redm[t][3]));
    __syncthreads();
#pragma unroll
    for (int mt = 0; mt < 4; mt++)
#pragma unroll
        for (int h = 0; h < 2; h++) {
            int r = wm * 64 + mt * 16 + fr + 8 * h;
            float rmx = redmax[r];
            float s = 0.0f;
#pragma unroll
            for (int nt = 0; nt < 4; nt++) {
                s += __expf(acc[mt][nt][2 * h]     * scale - rmx);
                s += __expf(acc[mt][nt][2 * h + 1] * scale - rmx);
            }
#pragma unroll
            for (int o = 1; o <= 2; o <<= 1)
                s += __shfl_xor_sync(0xffffffffu, s, o);
            if ((lane & 3) == 0) redl[r][wn] = s;
        }
    __syncthreads();
    if (t < 128) {
        float sum = redl[t][0] + redl[t][1] + redl[t][2] + redl[t][3];
        size_t o = ((size_t)blockIdx.z * LL + m0 + t) * NJT + blockIdx.x;
        pm[o] = redmax[t];
        ps[o] = sum;
    }
}

// ---------------------------------------------------------------------------
// Combine partials
// ---------------------------------------------------------------------------
__global__ void __launch_bounds__(256)
combine(const float* __restrict__ pm, const float* __restrict__ ps,
        float* __restrict__ c)
{
    const int row = blockIdx.x * 8 + threadIdx.y;
    const int tx  = threadIdx.x;
    size_t base = (size_t)row * NJT + tx;
    float m = pm[base];
    float l = ps[base];
    float M = m;
#pragma unroll
    for (int o = 16; o > 0; o >>= 1)
        M = fmaxf(M, __shfl_xor_sync(0xffffffffu, M, o));
    float s = l * __expf(m - M);
#pragma unroll
    for (int o = 16; o > 0; o >>= 1)
        s += __shfl_xor_sync(0xffffffffu, s, o);
    if (tx == 0) c[row] = M + __logf(s);
}

// ---------------------------------------------------------------------------
// Fused output GEMM, 2-term: out = Ph @ (Vh + Vl)
// A operand = fp16 hi of exp(S - c) only; missing Pl*V term ~2^-12 rel (RMS).
// ---------------------------------------------------------------------------
#define AOS_SSZ  (32 * 132 * 4)            // 16896 per S buffer
#define AOS_AH   (2 * AOS_SSZ)             // 33792 (single A tile)
#define AOS_B0   (AOS_AH + OPSZ)           // 44032
#define AOS_DYN  (AOS_B0 + 2 * 2 * OPSZ)   // 84992 B

__global__ void __launch_bounds__(256, 2)
attn_out_fused(const float* __restrict__ S, const float* __restrict__ cst,
               const __half* __restrict__ Vth, const __half* __restrict__ Vtl,
               float* __restrict__ out)
{
    extern __shared__ __align__(16) char dyn[];
    __shared__ float sc[32];
    const uint32_t su = smem_u32p(dyn);

    const int t = threadIdx.x;
    const int wid = t >> 5, lane = t & 31;
    const int wm = wid >> 2;
    const int wn = wid & 3;
    const int fr = lane >> 2;
    const int fc = (lane & 3) * 2;
    const int lar = (lane & 7) + ((lane >> 3) & 1) * 8;
    const int lac = (lane >> 4) * 8;
    const int lbr = (lane & 7) + (lane >> 4) * 8;
    const int lbc = ((lane >> 3) & 1) * 8;

    const int b = blockIdx.z;
    const float* Sb  = S   + (size_t)b * LL * LL;
    const float* cb  = cst + (size_t)b * LL;
    const __half* Vh = Vth + (size_t)b * DD * LL;
    const __half* Vl = Vtl + (size_t)b * DD * LL;
    float* Ob = out + (size_t)b * LL * DD;

    const int j0 = blockIdx.y * 128;
    const int d0 = blockIdx.x * 128;

    float acc[4][4][4];
#pragma unroll
    for (int i = 0; i < 4; i++)
#pragma unroll
        for (int j = 0; j < 4; j++)
#pragma unroll
            for (int e = 0; e < 4; e++) acc[i][j][e] = 0.0f;

    const int srow = t >> 2;
    const int sq   = (t & 3) * 8;

    auto stageB = [&](int buf, int i0) {
        const uint32_t base = su + AOS_B0 + buf * (2 * OPSZ);
#pragma unroll
        for (int it = 0; it < 2; it++) {
            int row = srow + 64 * it;
            uint32_t so = base + row * PITCH + sq * 2;
            size_t e = (size_t)(d0 + row) * LL + i0 + sq;
            cp_async16(so,        Vh + e);
            cp_async16(so + OPSZ, Vl + e);
        }
    };
    auto stageS = [&](int buf, int i0) {
        const uint32_t base = su + buf * AOS_SSZ;
#pragma unroll
        for (int u = 0; u < 4; u++) {
            int idx = t + 256 * u;
            int row = idx >> 5;
            int c4  = (idx & 31) * 4;
            cp_async16(base + row * 528 + c4 * 4,
                       Sb + (size_t)(i0 + row) * LL + j0 + c4);
        }
    };

    const int nchunks = LL >> 5;       // 128
    stageB(0, 0);
    stageS(0, 0);
    CP_COMMIT();

    const int jl = t & 127;
    const int ih = (t >> 7) * 16;

    for (int kc = 0; kc < nchunks; kc++) {
        const int i0 = kc << 5;
        if (kc + 1 < nchunks) {
            stageB((kc + 1) & 1, i0 + 32);
            stageS((kc + 1) & 1, i0 + 32);
        }
        CP_COMMIT();
        CP_WAIT1();
        if (t < 32) sc[t] = cb[i0 + t];
        __syncthreads();

        // ---- transform: exp + fp16(hi only) + transpose into sAh [j][i] ----
        {
            const float* sSp = (const float*)(dyn + (kc & 1) * AOS_SSZ);
            __half2 hb[8];
#pragma unroll
            for (int ii = 0; ii < 16; ii += 2) {
                float s0 = sSp[(ih + ii)     * 132 + jl];
                float s1 = sSp[(ih + ii + 1) * 132 + jl];
                float p0 = __expf(s0 - sc[ih + ii]);
                float p1 = __expf(s1 - sc[ih + ii + 1]);
                hb[ii >> 1] = __halves2half2(__float2half_rn(p0),
                                             __float2half_rn(p1));
            }
            char* ah = dyn + AOS_AH + jl * PITCH + ih * 2;
            *(uint4*)(ah)      = *(uint4*)&hb[0];
            *(uint4*)(ah + 16) = *(uint4*)&hb[4];
        }
        __syncthreads();

        // ---- 2-term MMA over the 32-i chunk: Ph*(Vh+Vl) ----
        const uint32_t aoh = su + AOS_AH;
        const uint32_t bbh = su + AOS_B0 + (kc & 1) * (2 * OPSZ);
        const uint32_t bbl = bbh + OPSZ;
#pragma unroll
        for (int ks = 0; ks < 32; ks += 16) {
            uint32_t ah[4][4], bh[4][2], bl[4][2];
#pragma unroll
            for (int mt = 0; mt < 4; mt++) {
                uint32_t ra = (uint32_t)(wm * 64 + mt * 16 + lar) * PITCH
                            + (ks + lac) * 2;
                ldm_x4(ah[mt], aoh + ra);
            }
#pragma unroll
            for (int pp = 0; pp < 2; pp++) {
                uint32_t rb = (uint32_t)(wn * 32 + pp * 16 + lbr) * PITCH
                            + (ks + lbc) * 2;
                uint32_t tb[4];
                ldm_x4(tb, bbh + rb);
                bh[2 * pp][0] = tb[0]; bh[2 * pp][1] = tb[1];
                bh[2 * pp + 1][0] = tb[2]; bh[2 * pp + 1][1] = tb[3];
                ldm_x4(tb, bbl + rb);
                bl[2 * pp][0] = tb[0]; bl[2 * pp][1] = tb[1];
                bl[2 * pp + 1][0] = tb[2]; bl[2 * pp + 1][1] = tb[3];
            }
#pragma unroll
            for (int mt = 0; mt < 4; mt++)
#pragma unroll
                for (int nt = 0; nt < 4; nt++) {
                    mma16816(acc[mt][nt], ah[mt], bh[nt]);
                    mma16816(acc[mt][nt], ah[mt], bl[nt]);
                }
        }
        __syncthreads();
    }

#pragma unroll
    for (int mt = 0; mt < 4; mt++) {
        int row = j0 + wm * 64 + mt * 16 + fr;
#pragma unroll
        for (int nt = 0; nt < 4; nt++) {
            int col = d0 + wn * 32 + nt * 8 + fc;
            float2 v0, v1;
            v0.x = acc[mt][nt][0];
            v0.y = acc[mt][nt][1];
            v1.x = acc[mt][nt][2];
            v1.y = acc[mt][nt][3];
            *(float2*)(Ob + (size_t)row * DD + col)       = v0;
            *(float2*)(Ob + (size_t)(row + 8) * DD + col) = v1;
        }
    }
}

// ---------------------------------------------------------------------------
// V^T build
// ---------------------------------------------------------------------------
__global__ void __launch_bounds__(256)
v_split_t(const float* __restrict__ V,
          __half* __restrict__ Vhi, __half* __restrict__ Vlo)
{
    const int b = blockIdx.z;
    const float* Vb = V + (size_t)b * LL * DD;
    __shared__ float tile[32][33];
    const int tx = threadIdx.x, ty = threadIdx.y;
    const int d0 = blockIdx.x * 32, i0 = blockIdx.y * 32;

#pragma unroll
    for (int r = 0; r < 4; r++) {
        int i = i0 + ty + r * 8;
        tile[ty + r * 8][tx] = Vb[(size_t)i * DD + d0 + tx];
    }
    __syncthreads();
    const size_t ob = (size_t)b * DD * LL;
#pragma unroll
    for (int r = 0; r < 4; r++) {
        int d = d0 + ty + r * 8;
        float v = tile[tx][ty + r * 8];
        __half h, l;
        split_half(v, h, l);
        size_t o = ob + (size_t)d * LL + i0 + tx;
        Vhi[o] = h;
        Vlo[o] = l;
    }
}

// ---------------------------------------------------------------------------
// Launch
// ---------------------------------------------------------------------------
extern "C" void kernel_launch(void* const* d_in, const int* in_sizes, int n_in,
                              void* d_out, int out_size)
{
    const float* q  = (const float*)d_in[0];
    const float* k  = (const float*)d_in[1];
    const float* v  = (const float*)d_in[2];
    const float* Wq = (const float*)d_in[3];
    const float* bq = (const float*)d_in[4];
    const float* Wk = (const float*)d_in[5];
    const float* bk = (const float*)d_in[6];
    const float* Wv = (const float*)d_in[7];
    const float* bv = (const float*)d_in[8];
    float* out = (float*)d_out;

    __half *xqh, *xql, *xkh, *xkl, *xvh, *xvl;
    __half *wqh, *wql, *wkh, *wkl, *wvh, *wvl;
    __half *qhi, *qlo, *khi, *klo, *vthi, *vtlo;
    float *vp, *S, *c, *pm, *ps;
    cudaGetSymbolAddress((void**)&xqh,  g_xqh);
    cudaGetSymbolAddress((void**)&xql,  g_xql);
    cudaGetSymbolAddress((void**)&xkh,  g_xkh);
    cudaGetSymbolAddress((void**)&xkl,  g_xkl);
    cudaGetSymbolAddress((void**)&xvh,  g_xvh);
    cudaGetSymbolAddress((void**)&xvl,  g_xvl);
    cudaGetSymbolAddress((void**)&wqh,  g_wqh);
    cudaGetSymbolAddress((void**)&wql,  g_wql);
    cudaGetSymbolAddress((void**)&wkh,  g_wkh);
    cudaGetSymbolAddress((void**)&wkl,  g_wkl);
    cudaGetSymbolAddress((void**)&wvh,  g_wvh);
    cudaGetSymbolAddress((void**)&wvl,  g_wvl);
    cudaGetSymbolAddress((void**)&qhi,  g_qhi);
    cudaGetSymbolAddress((void**)&qlo,  g_qlo);
    cudaGetSymbolAddress((void**)&khi,  g_khi);
    cudaGetSymbolAddress((void**)&klo,  g_klo);
    cudaGetSymbolAddress((void**)&vp,   g_vp);
    cudaGetSymbolAddress((void**)&S,    g_S);
    cudaGetSymbolAddress((void**)&c,    g_c);
    cudaGetSymbolAddress((void**)&pm,   g_pm);
    cudaGetSymbolAddress((void**)&ps,   g_ps);
    cudaGetSymbolAddress((void**)&vthi, g_vthi);
    cudaGetSymbolAddress((void**)&vtlo, g_vtlo);

    cudaFuncSetAttribute(proj_mma,
                         cudaFuncAttributeMaxDynamicSharedMemorySize, MMA_DYN);
    cudaFuncSetAttribute(score_mma,
                         cudaFuncAttributeMaxDynamicSharedMemorySize, MMA_DYN);
    cudaFuncSetAttribute(attn_out_fused,
                         cudaFuncAttributeMaxDynamicSharedMemorySize, AOS_DYN);

    const int NX = BB * LL * DD;
    const int NW = DD * DD;

    // 0) Split inputs + weights to fp16 hi/lo
    split2<<<NX / 1024, 256>>>(q, xqh, xql, NX);
    split2<<<NX / 1024, 256>>>(k, xkh, xkl, NX);
    split2<<<NX / 1024, 256>>>(v, xvh, xvl, NX);
    split2<<<NW / 1024, 256>>>(Wq, wqh, wql, NW);
    split2<<<NW / 1024, 256>>>(Wk, wkh, wkl, NW);
    split2<<<NW / 1024, 256>>>(Wv, wvh, wvl, NW);

    // 1) Projections on tensor cores
    dim3 gProj(DD / 128, (BB * LL) / 128, 1);
    proj_mma<<<gProj, 256, MMA_DYN>>>(xqh, xql, wqh, wql, bq, nullptr, qhi, qlo);
    proj_mma<<<gProj, 256, MMA_DYN>>>(xkh, xkl, wkh, wkl, bk, nullptr, khi, klo);
    proj_mma<<<gProj, 256, MMA_DYN>>>(xvh, xvl, wvh, wvl, bv, vp, nullptr, nullptr);

    // 2) V^T split
    v_split_t<<<dim3(DD / 32, LL / 32, BB), dim3(32, 8)>>>(vp, vthi, vtlo);

    // 3) Scores + per-tile softmax partials
    score_mma<<<dim3(LL / 128, LL / 128, BB), 256, MMA_DYN>>>(
        qhi, qlo, khi, klo, S, pm, ps, 0.0625f);

    // 4) Combine partials -> c
    combine<<<(BB * LL) / 8, dim3(32, 8)>>>(pm, ps, c);

    // 5) Fused output GEMM (2-term)
    attn_out_fused<<<dim3(DD / 128, LL / 128, BB), 256, AOS_DYN>>>(
        S, c, vthi, vtlo, out);
}

// round 12
// speedup vs baseline: 1.7048x; 1.2962x over previous
#include <cuda_runtime.h>
#include <cuda_fp16.h>
#include <cstdint>

#define BB   4
#define LL   4096
#define DD   256
#define NJT  (LL / 128)

// ---------------------------------------------------------------------------
// Device scratch (allocation-free)
// ---------------------------------------------------------------------------
__device__ __align__(256) __half g_xqh[BB * LL * DD];
__device__ __align__(256) __half g_xql[BB * LL * DD];
__device__ __align__(256) __half g_xkh[BB * LL * DD];
__device__ __align__(256) __half g_xkl[BB * LL * DD];
__device__ __align__(256) __half g_xvh[BB * LL * DD];
__device__ __align__(256) __half g_xvl[BB * LL * DD];
__device__ __align__(256) __half g_wqh[DD * DD];
__device__ __align__(256) __half g_wql[DD * DD];
__device__ __align__(256) __half g_wkh[DD * DD];
__device__ __align__(256) __half g_wkl[DD * DD];
__device__ __align__(256) __half g_wvh[DD * DD];
__device__ __align__(256) __half g_wvl[DD * DD];
__device__ __align__(256) __half g_qhi[BB * LL * DD];   // Q' hi (lo unused now)
__device__ __align__(256) __half g_khi[BB * LL * DD];
__device__ __align__(256) __half g_klo[BB * LL * DD];
__device__ __align__(256) float  g_vp [BB * LL * DD];
__device__ __align__(256) float  g_S  [(size_t)BB * LL * LL];
__device__ __align__(256) float  g_c  [BB * LL];
__device__ __align__(256) float  g_pm [(size_t)BB * LL * NJT];
__device__ __align__(256) float  g_ps [(size_t)BB * LL * NJT];
__device__ __align__(256) __half g_vthi[BB * DD * LL];

// ---------------------------------------------------------------------------
__device__ __forceinline__ void split_half(float x, __half& h, __half& l) {
    h = __float2half_rn(x);
    l = __float2half_rn(x - __half2float(h));
}

// ---------------------------------------------------------------------------
// Elementwise fp32 -> fp16 hi/lo split
// ---------------------------------------------------------------------------
__global__ void __launch_bounds__(256)
split2(const float* __restrict__ x, __half* __restrict__ h,
       __half* __restrict__ l, int n)
{
    int i = (blockIdx.x * 256 + threadIdx.x) * 4;
    if (i >= n) return;
    float4 v = *(const float4*)(x + i);
    __half h0, l0, h1, l1, h2, l2, h3, l3;
    split_half(v.x, h0, l0);
    split_half(v.y, h1, l1);
    split_half(v.z, h2, l2);
    split_half(v.w, h3, l3);
    __half2 hh01; hh01.x = h0; hh01.y = h1;
    __half2 hh23; hh23.x = h2; hh23.y = h3;
    __half2 ll01; ll01.x = l0; ll01.y = l1;
    __half2 ll23; ll23.x = l2; ll23.y = l3;
    *(__half2*)(h + i)     = hh01;
    *(__half2*)(h + i + 2) = hh23;
    *(__half2*)(l + i)     = ll01;
    *(__half2*)(l + i + 2) = ll23;
}

// ---------------------------------------------------------------------------
// mma.sync + ldmatrix + cp.async primitives
// ---------------------------------------------------------------------------
__device__ __forceinline__ void mma16816(float* d, const uint32_t* a, const uint32_t* b) {
    asm volatile(
        "mma.sync.aligned.m16n8k16.row.col.f32.f16.f16.f32 "
        "{%0,%1,%2,%3}, {%4,%5,%6,%7}, {%8,%9}, {%0,%1,%2,%3};"
        : "+f"(d[0]), "+f"(d[1]), "+f"(d[2]), "+f"(d[3])
        : "r"(a[0]), "r"(a[1]), "r"(a[2]), "r"(a[3]), "r"(b[0]), "r"(b[1]));
}
__device__ __forceinline__ void ldm_x4(uint32_t* r, uint32_t saddr) {
    asm volatile("ldmatrix.sync.aligned.m8n8.x4.shared.b16 {%0,%1,%2,%3}, [%4];"
                 : "=r"(r[0]), "=r"(r[1]), "=r"(r[2]), "=r"(r[3]) : "r"(saddr));
}
__device__ __forceinline__ uint32_t smem_u32p(const void* p) {
    uint32_t a;
    asm("{ .reg .u64 t; cvta.to.shared.u64 t, %1; cvt.u32.u64 %0, t; }"
        : "=r"(a) : "l"(p));
    return a;
}
__device__ __forceinline__ void cp_async16(uint32_t saddr, const void* g) {
    asm volatile("cp.async.cg.shared.global [%0], [%1], 16;"
                 :: "r"(saddr), "l"(g) : "memory");
}
#define CP_COMMIT()  asm volatile("cp.async.commit_group;" ::: "memory")
#define CP_WAIT1()   asm volatile("cp.async.wait_group 1;" ::: "memory")

#define SROW   40
#define PITCH  (SROW * 2)           // 80 B
#define OPSZ   (128 * PITCH)        // 10240 B
#define BUFSZ  (4 * OPSZ)
#define MMA_DYN (2 * BUFSZ)         // 81920 B (projections, 3-term)

// 3-term k16 step (projections only)
#define K16_STEP(ks, aoffh, aoffl, boffh, boffl)                               \
    do {                                                                       \
        uint32_t ah[4][4], al[4][4], bh[4][2], bl[4][2];                       \
        _Pragma("unroll")                                                      \
        for (int mt = 0; mt < 4; mt++) {                                       \
            uint32_t ra = (uint32_t)(wm * 64 + mt * 16 + lar) * PITCH          \
                        + ((ks) + lac) * 2;                                    \
            ldm_x4(ah[mt], (aoffh) + ra);                                      \
            ldm_x4(al[mt], (aoffl) + ra);                                      \
        }                                                                      \
        _Pragma("unroll")                                                      \
        for (int pp = 0; pp < 2; pp++) {                                       \
            uint32_t rb = (uint32_t)(wn * 32 + pp * 16 + lbr) * PITCH          \
                        + ((ks) + lbc) * 2;                                    \
            uint32_t tb[4];                                                    \
            ldm_x4(tb, (boffh) + rb);                                          \
            bh[2 * pp][0] = tb[0]; bh[2 * pp][1] = tb[1];                      \
            bh[2 * pp + 1][0] = tb[2]; bh[2 * pp + 1][1] = tb[3];              \
            ldm_x4(tb, (boffl) + rb);                                          \
            bl[2 * pp][0] = tb[0]; bl[2 * pp][1] = tb[1];                      \
            bl[2 * pp + 1][0] = tb[2]; bl[2 * pp + 1][1] = tb[3];              \
        }                                                                      \
        _Pragma("unroll")                                                      \
        for (int mt = 0; mt < 4; mt++)                                         \
            _Pragma("unroll")                                                  \
            for (int nt = 0; nt < 4; nt++) {                                   \
                mma16816(acc[mt][nt], ah[mt], bh[nt]);                         \
                mma16816(acc[mt][nt], ah[mt], bl[nt]);                         \
                mma16816(acc[mt][nt], al[mt], bh[nt]);                         \
            }                                                                  \
    } while (0)

// ---------------------------------------------------------------------------
// Projection GEMM on tensor cores (3-term, unchanged)
// ---------------------------------------------------------------------------
__global__ void __launch_bounds__(256, 2)
proj_mma(const __half* __restrict__ Xh, const __half* __restrict__ Xl,
         const __half* __restrict__ Wh, const __half* __restrict__ Wl,
         const float* __restrict__ bias, float* __restrict__ Cf,
         __half* __restrict__ Oh, __half* __restrict__ Ol)
{
    extern __shared__ __align__(16) char dyn[];
    const uint32_t su = smem_u32p(dyn);

    const int t = threadIdx.x;
    const int wid = t >> 5, lane = t & 31;
    const int wm = wid >> 2;
    const int wn = wid & 3;
    const int fr = lane >> 2;
    const int fc = (lane & 3) * 2;
    const int lar = (lane & 7) + ((lane >> 3) & 1) * 8;
    const int lac = (lane >> 4) * 8;
    const int lbr = (lane & 7) + (lane >> 4) * 8;
    const int lbc = ((lane >> 3) & 1) * 8;

    const int m0 = blockIdx.y * 128;
    const int n0 = blockIdx.x * 128;

    float acc[4][4][4];
#pragma unroll
    for (int i = 0; i < 4; i++)
#pragma unroll
        for (int j = 0; j < 4; j++)
#pragma unroll
            for (int e = 0; e < 4; e++) acc[i][j][e] = 0.0f;

    const int srow = t >> 2;
    const int sq   = (t & 3) * 8;

    auto stage = [&](int b, int k0) {
        const uint32_t base = su + b * BUFSZ;
#pragma unroll
        for (int it = 0; it < 2; it++) {
            int row = srow + 64 * it;
            uint32_t so = base + row * PITCH + sq * 2;
            size_t ea = (size_t)(m0 + row) * DD + k0 + sq;
            size_t eb = (size_t)(n0 + row) * DD + k0 + sq;
            cp_async16(so + 0 * OPSZ, Xh + ea);
            cp_async16(so + 1 * OPSZ, Xl + ea);
            cp_async16(so + 2 * OPSZ, Wh + eb);
            cp_async16(so + 3 * OPSZ, Wl + eb);
        }
    };

    const int nchunks = DD >> 5;
    stage(0, 0);
    CP_COMMIT();

    for (int kc = 0; kc < nchunks; kc++) {
        if (kc + 1 < nchunks) stage((kc + 1) & 1, (kc + 1) << 5);
        CP_COMMIT();
        CP_WAIT1();
        __syncthreads();

        const uint32_t bb = su + (kc & 1) * BUFSZ;
        K16_STEP(0,  bb, bb + OPSZ, bb + 2 * OPSZ, bb + 3 * OPSZ);
        K16_STEP(16, bb, bb + OPSZ, bb + 2 * OPSZ, bb + 3 * OPSZ);
        __syncthreads();
    }

#pragma unroll
    for (int mt = 0; mt < 4; mt++) {
#pragma unroll
        for (int h = 0; h < 2; h++) {
            int row = m0 + wm * 64 + mt * 16 + fr + 8 * h;
            size_t rowoff = (size_t)row * DD;
#pragma unroll
            for (int nt = 0; nt < 4; nt++) {
                int col = n0 + wn * 32 + nt * 8 + fc;
                float vx = acc[mt][nt][2 * h]     + bias[col];
                float vy = acc[mt][nt][2 * h + 1] + bias[col + 1];
                if (Oh) {
                    __half h0, l0, h1, l1;
                    split_half(vx, h0, l0);
                    split_half(vy, h1, l1);
                    __half2 hh; hh.x = h0; hh.y = h1;
                    *(__half2*)(Oh + rowoff + col) = hh;
                    if (Ol) {
                        __half2 ll; ll.x = l0; ll.y = l1;
                        *(__half2*)(Ol + rowoff + col) = ll;
                    }
                } else {
                    float2 vv; vv.x = vx; vv.y = vy;
                    *(float2*)(Cf + rowoff + col) = vv;
                }
            }
        }
    }
}

// ---------------------------------------------------------------------------
// Score GEMM (2-term: qh*(kh+kl)) + per-tile softmax partials
// ---------------------------------------------------------------------------
#define BUFSZ3   (3 * OPSZ)          // 30720 per buffer (Ah, Bh, Bl)
#define SCORE_DYN (2 * BUFSZ3)       // 61440

__global__ void __launch_bounds__(256, 2)
score_mma(const __half* __restrict__ Ahg,
          const __half* __restrict__ Bhg, const __half* __restrict__ Blg,
          float* __restrict__ C, float* __restrict__ pm, float* __restrict__ ps,
          float scale)
{
    extern __shared__ __align__(16) char dyn[];
    const uint32_t su = smem_u32p(dyn);
    __shared__ float redm[128][4];
    __shared__ float redl[128][4];
    __shared__ float redmax[128];

    const int t = threadIdx.x;
    const int wid = t >> 5, lane = t & 31;
    const int wm = wid >> 2;
    const int wn = wid & 3;
    const int fr = lane >> 2;
    const int fc = (lane & 3) * 2;
    const int lar = (lane & 7) + ((lane >> 3) & 1) * 8;
    const int lac = (lane >> 4) * 8;
    const int lbr = (lane & 7) + (lane >> 4) * 8;
    const int lbc = ((lane >> 3) & 1) * 8;

    const size_t zqk = (size_t)LL * DD;
    Ahg += (size_t)blockIdx.z * zqk;
    Bhg += (size_t)blockIdx.z * zqk;  Blg += (size_t)blockIdx.z * zqk;
    C   += (size_t)blockIdx.z * LL * LL;
    const int m0 = blockIdx.y * 128;
    const int n0 = blockIdx.x * 128;

    float acc[4][4][4];
#pragma unroll
    for (int i = 0; i < 4; i++)
#pragma unroll
        for (int j = 0; j < 4; j++)
#pragma unroll
            for (int e = 0; e < 4; e++) acc[i][j][e] = 0.0f;

    const int srow = t >> 2;
    const int sq   = (t & 3) * 8;

    auto stage = [&](int b, int k0) {
        const uint32_t base = su + b * BUFSZ3;
#pragma unroll
        for (int it = 0; it < 2; it++) {
            int row = srow + 64 * it;
            uint32_t so = base + row * PITCH + sq * 2;
            size_t ea = (size_t)(m0 + row) * DD + k0 + sq;
            size_t eb = (size_t)(n0 + row) * DD + k0 + sq;
            cp_async16(so + 0 * OPSZ, Ahg + ea);
            cp_async16(so + 1 * OPSZ, Bhg + eb);
            cp_async16(so + 2 * OPSZ, Blg + eb);
        }
    };

    const int nchunks = DD >> 5;
    stage(0, 0);
    CP_COMMIT();

    for (int kc = 0; kc < nchunks; kc++) {
        if (kc + 1 < nchunks) stage((kc + 1) & 1, (kc + 1) << 5);
        CP_COMMIT();
        CP_WAIT1();
        __syncthreads();

        const uint32_t aoh = su + (kc & 1) * BUFSZ3;
        const uint32_t bbh = aoh + OPSZ;
        const uint32_t bbl = aoh + 2 * OPSZ;
#pragma unroll
        for (int ks = 0; ks < 32; ks += 16) {
            uint32_t ah[4][4], bh[4][2], bl[4][2];
#pragma unroll
            for (int mt = 0; mt < 4; mt++) {
                uint32_t ra = (uint32_t)(wm * 64 + mt * 16 + lar) * PITCH
                            + (ks + lac) * 2;
                ldm_x4(ah[mt], aoh + ra);
            }
#pragma unroll
            for (int pp = 0; pp < 2; pp++) {
                uint32_t rb = (uint32_t)(wn * 32 + pp * 16 + lbr) * PITCH
                            + (ks + lbc) * 2;
                uint32_t tb[4];
                ldm_x4(tb, bbh + rb);
                bh[2 * pp][0] = tb[0]; bh[2 * pp][1] = tb[1];
                bh[2 * pp + 1][0] = tb[2]; bh[2 * pp + 1][1] = tb[3];
                ldm_x4(tb, bbl + rb);
                bl[2 * pp][0] = tb[0]; bl[2 * pp][1] = tb[1];
                bl[2 * pp + 1][0] = tb[2]; bl[2 * pp + 1][1] = tb[3];
            }
#pragma unroll
            for (int mt = 0; mt < 4; mt++)
#pragma unroll
                for (int nt = 0; nt < 4; nt++) {
                    mma16816(acc[mt][nt], ah[mt], bh[nt]);
                    mma16816(acc[mt][nt], ah[mt], bl[nt]);
                }
        }
        __syncthreads();
    }

#pragma unroll
    for (int mt = 0; mt < 4; mt++) {
        int row = m0 + wm * 64 + mt * 16 + fr;
#pragma unroll
        for (int nt = 0; nt < 4; nt++) {
            int col = n0 + wn * 32 + nt * 8 + fc;
            float2 v0, v1;
            v0.x = acc[mt][nt][0] * scale;
            v0.y = acc[mt][nt][1] * scale;
            v1.x = acc[mt][nt][2] * scale;
            v1.y = acc[mt][nt][3] * scale;
            *(float2*)(C + (size_t)row * LL + col)       = v0;
            *(float2*)(C + (size_t)(row + 8) * LL + col) = v1;
        }
    }

    float rm[4][2];
#pragma unroll
    for (int mt = 0; mt < 4; mt++)
#pragma unroll
        for (int h = 0; h < 2; h++) {
            float m = -3.0e38f;
#pragma unroll
            for (int nt = 0; nt < 4; nt++) {
                m = fmaxf(m, acc[mt][nt][2 * h]     * scale);
                m = fmaxf(m, acc[mt][nt][2 * h + 1] * scale);
            }
#pragma unroll
            for (int o = 1; o <= 2; o <<= 1)
                m = fmaxf(m, __shfl_xor_sync(0xffffffffu, m, o));
            rm[mt][h] = m;
        }
    if ((lane & 3) == 0) {
#pragma unroll
        for (int mt = 0; mt < 4; mt++)
#pragma unroll
            for (int h = 0; h < 2; h++)
                redm[wm * 64 + mt * 16 + fr + 8 * h][wn] = rm[mt][h];
    }
    __syncthreads();
    if (t < 128)
        redmax[t] = fmaxf(fmaxf(redm[t][0], redm[t][1]),
                          fmaxf(redm[t][2], redm[t][3]));
    __syncthreads();
#pragma unroll
    for (int mt = 0; mt < 4; mt++)
#pragma unroll
        for (int h = 0; h < 2; h++) {
            int r = wm * 64 + mt * 16 + fr + 8 * h;
            float rmx = redmax[r];
            float s = 0.0f;
#pragma unroll
            for (int nt = 0; nt < 4; nt++) {
                s += __expf(acc[mt][nt][2 * h]     * scale - rmx);
                s += __expf(acc[mt][nt][2 * h + 1] * scale - rmx);
            }
#pragma unroll
            for (int o = 1; o <= 2; o <<= 1)
                s += __shfl_xor_sync(0xffffffffu, s, o);
            if ((lane & 3) == 0) redl[r][wn] = s;
        }
    __syncthreads();
    if (t < 128) {
        float sum = redl[t][0] + redl[t][1] + redl[t][2] + redl[t][3];
        size_t o = ((size_t)blockIdx.z * LL + m0 + t) * NJT + blockIdx.x;
        pm[o] = redmax[t];
        ps[o] = sum;
    }
}

// ---------------------------------------------------------------------------
// Combine partials
// ---------------------------------------------------------------------------
__global__ void __launch_bounds__(256)
combine(const float* __restrict__ pm, const float* __restrict__ ps,
        float* __restrict__ c)
{
    const int row = blockIdx.x * 8 + threadIdx.y;
    const int tx  = threadIdx.x;
    size_t base = (size_t)row * NJT + tx;
    float m = pm[base];
    float l = ps[base];
    float M = m;
#pragma unroll
    for (int o = 16; o > 0; o >>= 1)
        M = fmaxf(M, __shfl_xor_sync(0xffffffffu, M, o));
    float s = l * __expf(m - M);
#pragma unroll
    for (int o = 16; o > 0; o >>= 1)
        s += __shfl_xor_sync(0xffffffffu, s, o);
    if (tx == 0) c[row] = M + __logf(s);
}

// ---------------------------------------------------------------------------
// Fused output GEMM, 1-term: out = Ph @ Vh
// ---------------------------------------------------------------------------
#define AOS_SSZ  (32 * 132 * 4)            // 16896 per S buffer
#define AOS_AH   (2 * AOS_SSZ)             // 33792 (single A tile)
#define AOS_B0   (AOS_AH + OPSZ)           // 44032 (2 x 10240 Vh buffers)
#define AOS_DYN  (AOS_B0 + 2 * OPSZ)       // 64512 B

__global__ void __launch_bounds__(256, 2)
attn_out_fused(const float* __restrict__ S, const float* __restrict__ cst,
               const __half* __restrict__ Vth, float* __restrict__ out)
{
    extern __shared__ __align__(16) char dyn[];
    __shared__ float sc[32];
    const uint32_t su = smem_u32p(dyn);

    const int t = threadIdx.x;
    const int wid = t >> 5, lane = t & 31;
    const int wm = wid >> 2;
    const int wn = wid & 3;
    const int fr = lane >> 2;
    const int fc = (lane & 3) * 2;
    const int lar = (lane & 7) + ((lane >> 3) & 1) * 8;
    const int lac = (lane >> 4) * 8;
    const int lbr = (lane & 7) + (lane >> 4) * 8;
    const int lbc = ((lane >> 3) & 1) * 8;

    const int b = blockIdx.z;
    const float* Sb  = S   + (size_t)b * LL * LL;
    const float* cb  = cst + (size_t)b * LL;
    const __half* Vh = Vth + (size_t)b * DD * LL;
    float* Ob = out + (size_t)b * LL * DD;

    const int j0 = blockIdx.y * 128;
    const int d0 = blockIdx.x * 128;

    float acc[4][4][4];
#pragma unroll
    for (int i = 0; i < 4; i++)
#pragma unroll
        for (int j = 0; j < 4; j++)
#pragma unroll
            for (int e = 0; e < 4; e++) acc[i][j][e] = 0.0f;

    const int srow = t >> 2;
    const int sq   = (t & 3) * 8;

    auto stageB = [&](int buf, int i0) {
        const uint32_t base = su + AOS_B0 + buf * OPSZ;
#pragma unroll
        for (int it = 0; it < 2; it++) {
            int row = srow + 64 * it;
            uint32_t so = base + row * PITCH + sq * 2;
            cp_async16(so, Vh + (size_t)(d0 + row) * LL + i0 + sq);
        }
    };
    auto stageS = [&](int buf, int i0) {
        const uint32_t base = su + buf * AOS_SSZ;
#pragma unroll
        for (int u = 0; u < 4; u++) {
            int idx = t + 256 * u;
            int row = idx >> 5;
            int c4  = (idx & 31) * 4;
            cp_async16(base + row * 528 + c4 * 4,
                       Sb + (size_t)(i0 + row) * LL + j0 + c4);
        }
    };

    const int nchunks = LL >> 5;       // 128
    stageB(0, 0);
    stageS(0, 0);
    CP_COMMIT();

    const int jl = t & 127;
    const int ih = (t >> 7) * 16;

    for (int kc = 0; kc < nchunks; kc++) {
        const int i0 = kc << 5;
        if (kc + 1 < nchunks) {
            stageB((kc + 1) & 1, i0 + 32);
            stageS((kc + 1) & 1, i0 + 32);
        }
        CP_COMMIT();
        CP_WAIT1();
        if (t < 32) sc[t] = cb[i0 + t];
        __syncthreads();

        // ---- transform: exp + fp16(hi) + transpose into sAh [j][i] ----
        {
            const float* sSp = (const float*)(dyn + (kc & 1) * AOS_SSZ);
            __half2 hb[8];
#pragma unroll
            for (int ii = 0; ii < 16; ii += 2) {
                float s0 = sSp[(ih + ii)     * 132 + jl];
                float s1 = sSp[(ih + ii + 1) * 132 + jl];
                float p0 = __expf(s0 - sc[ih + ii]);
                float p1 = __expf(s1 - sc[ih + ii + 1]);
                hb[ii >> 1] = __halves2half2(__float2half_rn(p0),
                                             __float2half_rn(p1));
            }
            char* ah = dyn + AOS_AH + jl * PITCH + ih * 2;
            *(uint4*)(ah)      = *(uint4*)&hb[0];
            *(uint4*)(ah + 16) = *(uint4*)&hb[4];
        }
        __syncthreads();

        // ---- 1-term MMA over the 32-i chunk: Ph*Vh ----
        const uint32_t aoh = su + AOS_AH;
        const uint32_t bbh = su + AOS_B0 + (kc & 1) * OPSZ;
#pragma unroll
        for (int ks = 0; ks < 32; ks += 16) {
            uint32_t ah[4][4], bh[4][2];
#pragma unroll
            for (int mt = 0; mt < 4; mt++) {
                uint32_t ra = (uint32_t)(wm * 64 + mt * 16 + lar) * PITCH
                            + (ks + lac) * 2;
                ldm_x4(ah[mt], aoh + ra);
            }
#pragma unroll
            for (int pp = 0; pp < 2; pp++) {
                uint32_t rb = (uint32_t)(wn * 32 + pp * 16 + lbr) * PITCH
                            + (ks + lbc) * 2;
                uint32_t tb[4];
                ldm_x4(tb, bbh + rb);
                bh[2 * pp][0] = tb[0]; bh[2 * pp][1] = tb[1];
                bh[2 * pp + 1][0] = tb[2]; bh[2 * pp + 1][1] = tb[3];
            }
#pragma unroll
            for (int mt = 0; mt < 4; mt++)
#pragma unroll
                for (int nt = 0; nt < 4; nt++)
                    mma16816(acc[mt][nt], ah[mt], bh[nt]);
        }
        __syncthreads();
    }

#pragma unroll
    for (int mt = 0; mt < 4; mt++) {
        int row = j0 + wm * 64 + mt * 16 + fr;
#pragma unroll
        for (int nt = 0; nt < 4; nt++) {
            int col = d0 + wn * 32 + nt * 8 + fc;
            float2 v0, v1;
            v0.x = acc[mt][nt][0];
            v0.y = acc[mt][nt][1];
            v1.x = acc[mt][nt][2];
            v1.y = acc[mt][nt][3];
            *(float2*)(Ob + (size_t)row * DD + col)       = v0;
            *(float2*)(Ob + (size_t)(row + 8) * DD + col) = v1;
        }
    }
}

// ---------------------------------------------------------------------------
// V^T build (hi only)
// ---------------------------------------------------------------------------
__global__ void __launch_bounds__(256)
v_split_t(const float* __restrict__ V, __half* __restrict__ Vhi)
{
    const int b = blockIdx.z;
    const float* Vb = V + (size_t)b * LL * DD;
    __shared__ float tile[32][33];
    const int tx = threadIdx.x, ty = threadIdx.y;
    const int d0 = blockIdx.x * 32, i0 = blockIdx.y * 32;

#pragma unroll
    for (int r = 0; r < 4; r++) {
        int i = i0 + ty + r * 8;
        tile[ty + r * 8][tx] = Vb[(size_t)i * DD + d0 + tx];
    }
    __syncthreads();
    const size_t ob = (size_t)b * DD * LL;
#pragma unroll
    for (int r = 0; r < 4; r++) {
        int d = d0 + ty + r * 8;
        Vhi[ob + (size_t)d * LL + i0 + tx] =
            __float2half_rn(tile[tx][ty + r * 8]);
    }
}

// ---------------------------------------------------------------------------
// Launch
// ---------------------------------------------------------------------------
extern "C" void kernel_launch(void* const* d_in, const int* in_sizes, int n_in,
                              void* d_out, int out_size)
{
    const float* q  = (const float*)d_in[0];
    const float* k  = (const float*)d_in[1];
    const float* v  = (const float*)d_in[2];
    const float* Wq = (const float*)d_in[3];
    const float* bq = (const float*)d_in[4];
    const float* Wk = (const float*)d_in[5];
    const float* bk = (const float*)d_in[6];
    const float* Wv = (const float*)d_in[7];
    const float* bv = (const float*)d_in[8];
    float* out = (float*)d_out;

    __half *xqh, *xql, *xkh, *xkl, *xvh, *xvl;
    __half *wqh, *wql, *wkh, *wkl, *wvh, *wvl;
    __half *qhi, *khi, *klo, *vthi;
    float *vp, *S, *c, *pm, *ps;
    cudaGetSymbolAddress((void**)&xqh,  g_xqh);
    cudaGetSymbolAddress((void**)&xql,  g_xql);
    cudaGetSymbolAddress((void**)&xkh,  g_xkh);
    cudaGetSymbolAddress((void**)&xkl,  g_xkl);
    cudaGetSymbolAddress((void**)&xvh,  g_xvh);
    cudaGetSymbolAddress((void**)&xvl,  g_xvl);
    cudaGetSymbolAddress((void**)&wqh,  g_wqh);
    cudaGetSymbolAddress((void**)&wql,  g_wql);
    cudaGetSymbolAddress((void**)&wkh,  g_wkh);
    cudaGetSymbolAddress((void**)&wkl,  g_wkl);
    cudaGetSymbolAddress((void**)&wvh,  g_wvh);
    cudaGetSymbolAddress((void**)&wvl,  g_wvl);
    cudaGetSymbolAddress((void**)&qhi,  g_qhi);
    cudaGetSymbolAddress((void**)&khi,  g_khi);
    cudaGetSymbolAddress((void**)&klo,  g_klo);
    cudaGetSymbolAddress((void**)&vp,   g_vp);
    cudaGetSymbolAddress((void**)&S,    g_S);
    cudaGetSymbolAddress((void**)&c,    g_c);
    cudaGetSymbolAddress((void**)&pm,   g_pm);
    cudaGetSymbolAddress((void**)&ps,   g_ps);
    cudaGetSymbolAddress((void**)&vthi, g_vthi);

    cudaFuncSetAttribute(proj_mma,
                         cudaFuncAttributeMaxDynamicSharedMemorySize, MMA_DYN);
    cudaFuncSetAttribute(score_mma,
                         cudaFuncAttributeMaxDynamicSharedMemorySize, SCORE_DYN);
    cudaFuncSetAttribute(attn_out_fused,
                         cudaFuncAttributeMaxDynamicSharedMemorySize, AOS_DYN);

    const int NX = BB * LL * DD;
    const int NW = DD * DD;

    // 0) Split inputs + weights to fp16 hi/lo
    split2<<<NX / 1024, 256>>>(q, xqh, xql, NX);
    split2<<<NX / 1024, 256>>>(k, xkh, xkl, NX);
    split2<<<NX / 1024, 256>>>(v, xvh, xvl, NX);
    split2<<<NW / 1024, 256>>>(Wq, wqh, wql, NW);
    split2<<<NW / 1024, 256>>>(Wk, wkh, wkl, NW);
    split2<<<NW / 1024, 256>>>(Wv, wvh, wvl, NW);

    // 1) Projections on tensor cores (Q: hi only; K: hi+lo; V: fp32)
    dim3 gProj(DD / 128, (BB * LL) / 128, 1);
    proj_mma<<<gProj, 256, MMA_DYN>>>(xqh, xql, wqh, wql, bq, nullptr, qhi, nullptr);
    proj_mma<<<gProj, 256, MMA_DYN>>>(xkh, xkl, wkh, wkl, bk, nullptr, khi, klo);
    proj_mma<<<gProj, 256, MMA_DYN>>>(xvh, xvl, wvh, wvl, bv, vp, nullptr, nullptr);

    // 2) V^T (hi only)
    v_split_t<<<dim3(DD / 32, LL / 32, BB), dim3(32, 8)>>>(vp, vthi);

    // 3) Scores (2-term) + per-tile softmax partials
    score_mma<<<dim3(LL / 128, LL / 128, BB), 256, SCORE_DYN>>>(
        qhi, khi, klo, S, pm, ps, 0.0625f);

    // 4) Combine partials -> c
    combine<<<(BB * LL) / 8, dim3(32, 8)>>>(pm, ps, c);

    // 5) Fused output GEMM (1-term)
    attn_out_fused<<<dim3(DD / 128, LL / 128, BB), 256, AOS_DYN>>>(
        S, c, vthi, out);
}